// round 9
// baseline (speedup 1.0000x reference)
#include <cuda_runtime.h>
#include <cstdint>

typedef unsigned long long ULL;

#define B_   64
#define S_   1024
#define I_   1024
#define H_   1024
#define SH_  (S_ * H_)   // 1048576

// ---- packed f32x2 helpers ----
__device__ __forceinline__ void fma2(ULL& d, ULL a, ULL b) {
    asm("fma.rn.f32x2 %0, %1, %2, %0;" : "+l"(d) : "l"(a), "l"(b));
}
__device__ __forceinline__ float pairsum(ULL v) {
    union { ULL u; float2 f; } t;
    t.u = v;
    return t.f.x + t.f.y;
}
__device__ __forceinline__ void cp_async16(uint32_t smem_addr, const void* gptr) {
    asm volatile("cp.async.cg.shared.global [%0], [%1], 16;"
                 :: "r"(smem_addr), "l"(gptr));
}
__device__ __forceinline__ uint32_t smem_u32(const void* p) {
    return (uint32_t)__cvta_generic_to_shared(p);
}
// pack: low half = bf16(v0), high half = bf16(v1)
__device__ __forceinline__ uint32_t pack_bf16(float v0, float v1) {
    uint32_t r;
    asm("cvt.rn.bf16x2.f32 %0, %1, %2;" : "=r"(r) : "f"(v1), "f"(v0));
    return r;
}

// ============================================================================
// Static scratch: split-bf16 copies of x and Wih (u32 = 2 packed bf16).
// ============================================================================
__device__ unsigned g_xhi[33554432];   // 64M bf16 = 128 MB
__device__ unsigned g_xlo[33554432];
__device__ unsigned g_whi[524288];     // 1M bf16
__device__ unsigned g_wlo[524288];

// ============================================================================
// Convert fp32 -> (hi, lo) bf16 pairs. which: 0 = x, 1 = W.
// ============================================================================
__global__ void cvt_split(const float* __restrict__ src, int which, int n4)
{
    unsigned* hi = which ? g_whi : g_xhi;
    unsigned* lo = which ? g_wlo : g_xlo;
    int stride = gridDim.x * blockDim.x;
    for (int i = blockIdx.x * blockDim.x + threadIdx.x; i < n4; i += stride) {
        float4 v = ((const float4*)src)[i];
        uint32_t h0 = pack_bf16(v.x, v.y);
        uint32_t h1 = pack_bf16(v.z, v.w);
        float l0 = v.x - __uint_as_float(h0 << 16);
        float l1 = v.y - __uint_as_float(h0 & 0xFFFF0000u);
        float l2 = v.z - __uint_as_float(h1 << 16);
        float l3 = v.w - __uint_as_float(h1 & 0xFFFF0000u);
        hi[2 * i]     = h0;
        hi[2 * i + 1] = h1;
        lo[2 * i]     = pack_bf16(l0, l1);
        lo[2 * i + 1] = pack_bf16(l2, l3);
    }
}

// ============================================================================
// wx_mma: y[m,n] = sum_k x[m,k] * Wih[n,k] + bias[n] via split-bf16 HMMA.
// (unchanged from R8 — passing at ~1 ms)
// ============================================================================
#define STG_BYTES 30720
#define A_LO_OFF  10240
#define B_OFF     20480
#define B_LO_OFF  25600

__device__ __forceinline__ void mma_bf16(float& c0, float& c1, float& c2, float& c3,
                                         uint32_t a0, uint32_t a1, uint32_t a2, uint32_t a3,
                                         uint32_t b0, uint32_t b1) {
    asm volatile("mma.sync.aligned.m16n8k16.row.col.f32.bf16.bf16.f32 "
                 "{%0,%1,%2,%3}, {%4,%5,%6,%7}, {%8,%9}, {%0,%1,%2,%3};"
                 : "+f"(c0), "+f"(c1), "+f"(c2), "+f"(c3)
                 : "r"(a0), "r"(a1), "r"(a2), "r"(a3), "r"(b0), "r"(b1));
}

__global__ __launch_bounds__(256, 2)
void wx_mma(const float* __restrict__ bias, float* __restrict__ y)
{
    extern __shared__ __align__(16) char smem[];
    const uint32_t sbase = smem_u32(smem);

    const int tid  = threadIdx.x;
    const int wid  = tid >> 5;
    const int lane = tid & 31;
    const int g    = lane >> 2;
    const int t    = lane & 3;
    const int wm   = wid & 3;
    const int wn   = wid >> 2;
    const int m0   = blockIdx.y * 128;
    const int n0   = blockIdx.x * 64;

    float acc[2][4][4];
#pragma unroll
    for (int mf = 0; mf < 2; mf++)
#pragma unroll
        for (int nf = 0; nf < 4; nf++)
#pragma unroll
            for (int c = 0; c < 4; c++) acc[mf][nf][c] = 0.0f;

    auto issue = [&](int st) {
        const uint32_t d = sbase + (st & 1) * STG_BYTES;
        const int k0 = st * 32;
#pragma unroll
        for (int r = 0; r < 4; r++) {
            int id   = tid + 256 * r;
            int part = id >> 9;
            int rem  = id & 511;
            int row  = rem >> 2;
            int seg  = rem & 3;
            const unsigned* srcb = part ? g_xlo : g_xhi;
            const char* src = (const char*)(srcb +
                ((size_t)(m0 + row) * 1024 + k0) / 2) + seg * 16;
            cp_async16(d + part * A_LO_OFF + row * 80 + seg * 16, src);
        }
#pragma unroll
        for (int r = 0; r < 2; r++) {
            int id   = tid + 256 * r;
            int part = id >> 8;
            int rem  = id & 255;
            int row  = rem >> 2;
            int seg  = rem & 3;
            const unsigned* srcb = part ? g_wlo : g_whi;
            const char* src = (const char*)(srcb +
                ((size_t)(n0 + row) * 1024 + k0) / 2) + seg * 16;
            cp_async16(d + B_OFF + part * 5120 + row * 80 + seg * 16, src);
        }
        asm volatile("cp.async.commit_group;" ::: "memory");
    };

    issue(0);
    for (int i = 0; i < 32; i++) {
        if (i + 1 < 32) {
            issue(i + 1);
            asm volatile("cp.async.wait_group 1;" ::: "memory");
        } else {
            asm volatile("cp.async.wait_group 0;" ::: "memory");
        }
        __syncthreads();

        const char* sm  = smem + (i & 1) * STG_BYTES;
        const char* Ahi = sm;
        const char* Alo = sm + A_LO_OFF;
        const char* Bhi = sm + B_OFF;
        const char* Blo = sm + B_LO_OFF;

#pragma unroll
        for (int ks = 0; ks < 32; ks += 16) {
            const int colb = (ks + t * 2) * 2;
            uint32_t ah[2][4], al[2][4];
#pragma unroll
            for (int mf = 0; mf < 2; mf++) {
                int r0 = (wm * 32 + mf * 16 + g) * 80;
                int r1 = r0 + 8 * 80;
                ah[mf][0] = *(const uint32_t*)(Ahi + r0 + colb);
                ah[mf][1] = *(const uint32_t*)(Ahi + r1 + colb);
                ah[mf][2] = *(const uint32_t*)(Ahi + r0 + colb + 16);
                ah[mf][3] = *(const uint32_t*)(Ahi + r1 + colb + 16);
                al[mf][0] = *(const uint32_t*)(Alo + r0 + colb);
                al[mf][1] = *(const uint32_t*)(Alo + r1 + colb);
                al[mf][2] = *(const uint32_t*)(Alo + r0 + colb + 16);
                al[mf][3] = *(const uint32_t*)(Alo + r1 + colb + 16);
            }
            uint32_t bh[4][2], bl[4][2];
#pragma unroll
            for (int nf = 0; nf < 4; nf++) {
                int nr = (wn * 32 + nf * 8 + g) * 80;
                bh[nf][0] = *(const uint32_t*)(Bhi + nr + colb);
                bh[nf][1] = *(const uint32_t*)(Bhi + nr + colb + 16);
                bl[nf][0] = *(const uint32_t*)(Blo + nr + colb);
                bl[nf][1] = *(const uint32_t*)(Blo + nr + colb + 16);
            }
#pragma unroll
            for (int mf = 0; mf < 2; mf++)
#pragma unroll
                for (int nf = 0; nf < 4; nf++) {
                    float* c = acc[mf][nf];
                    mma_bf16(c[0], c[1], c[2], c[3],
                             ah[mf][0], ah[mf][1], ah[mf][2], ah[mf][3],
                             bh[nf][0], bh[nf][1]);
                    mma_bf16(c[0], c[1], c[2], c[3],
                             al[mf][0], al[mf][1], al[mf][2], al[mf][3],
                             bh[nf][0], bh[nf][1]);
                    mma_bf16(c[0], c[1], c[2], c[3],
                             ah[mf][0], ah[mf][1], ah[mf][2], ah[mf][3],
                             bl[nf][0], bl[nf][1]);
                }
        }
        __syncthreads();
    }

#pragma unroll
    for (int mf = 0; mf < 2; mf++) {
        int m = m0 + wm * 32 + mf * 16 + g;
#pragma unroll
        for (int nf = 0; nf < 4; nf++) {
            int n = n0 + wn * 32 + nf * 8 + t * 2;
            float2 bv = *(const float2*)(bias + n);
            float* c = acc[mf][nf];
            *(float2*)(y + (size_t)m * H_ + n) =
                make_float2(c[0] + bv.x, c[1] + bv.y);
            *(float2*)(y + (size_t)(m + 8) * H_ + n) =
                make_float2(c[2] + bv.x, c[3] + bv.y);
        }
    }
}

// ============================================================================
// Producer flags: one per CTA, on its own 128B line. Monotonic across
// replays (base re-read from own flag at launch entry).
// flag[(bg*32+ft)*32] == base + s + 1  <=>  CTA (ft,bg) finished writing y[s].
// ============================================================================
__device__ unsigned g_flag[128 * 32];

// ============================================================================
// Persistent recurrence with fine-grained producer-flag dataflow sync.
// Chunk c (128 K) of step s depends only on producers 4c..4c+3 of step s-1.
// Each thread polls exactly the flag covering its own cp.async K-range,
// then issues; compute of chunk c-1 overlaps transfer of chunk c.
// smem: wsm 32x1024 (128KB) + hs 16x1024 (64KB; reduce scratch aliases hs).
// ============================================================================
__global__ __launch_bounds__(256, 1)
void rnn_persistent(const float* __restrict__ h0,
                    const float* __restrict__ Whh,
                    const float* __restrict__ bias,
                    float* __restrict__ y,
                    float* __restrict__ hlast)
{
    extern __shared__ float smemf[];
    float* wsm = smemf;
    float* hs  = smemf + 32 * 1024;
    float (*red)[32][33] = (float (*)[32][33])hs;
    __shared__ unsigned sh_base;

    const int tid  = threadIdx.x;
    const int w    = tid >> 5;
    const int lane = tid & 31;
    const int fw   = w & 3;
    const int bw   = w >> 2;
    const int ft_id = blockIdx.x;          // 0..31 (ftile == producer index)
    const int bg_id = blockIdx.y;          // 0..3
    const int ftile = ft_id * 32;
    const int bg    = bg_id * 16;

    unsigned* my_flag = &g_flag[(bg_id * 32 + ft_id) * 32];
    if (tid == 0) {
        unsigned b0;
        asm volatile("ld.global.relaxed.gpu.u32 %0, [%1];" : "=r"(b0) : "l"(my_flag));
        sh_base = b0;
    }

    // ---- one-time: Whh slice into smem ----
#pragma unroll 4
    for (int r = 0; r < 32; r++) {
        int slot = r * 256 + tid;
        int f = slot >> 8;
        int c = (slot & 255) * 4;
        *(float4*)&wsm[f * 1024 + c] =
            *(const float4*)(Whh + (size_t)(ftile + f) * H_ + c);
    }

    const int fl  = lane >> 3;
    const int bl  = lane & 7;
    const int bgl = bg + bw * 8 + bl;
    const int fg0 = ftile + fw * 8 + 0 * 4 + fl;
    const int fg1 = ftile + fw * 8 + 1 * 4 + fl;
    float bias0 = bias[fg0];
    float bias1 = bias[fg1];
    float* yp0 = y + (size_t)bgl * SH_ + fg0;
    float* yp1 = y + (size_t)bgl * SH_ + fg1;

    const uint32_t hs_base = smem_u32(hs);

    // staging geometry: per chunk (128 K), thread has 2 tasks of 16B,
    // both at k-seg (tid&31) -> covered by exactly one producer.
    const int seg = tid & 31;              // float4 seg within chunk
    const int b0t = tid >> 5;              // batch row for task 0 (task 1: +8)
    const unsigned* poll_flag_base =
        &g_flag[(bg_id * 32 /* + producer added per chunk */) * 32];

    float wx0 = yp0[0];
    float wx1 = yp1[0];

    __syncthreads();
    const unsigned base = sh_base;

    for (int s = 0; s < S_; s++) {
        const float* hprev = (s == 0) ? h0 : (y + (size_t)(s - 1) * H_);
        const int hstride  = (s == 0) ? H_ : SH_;

        ULL acc[8][8];
#pragma unroll
        for (int f = 0; f < 8; f++)
#pragma unroll
            for (int b = 0; b < 8; b++) acc[f][b] = 0ull;

        // ---- dataflow pipeline over 8 chunks of 128 K ----
#pragma unroll 1
        for (int c = 0; c < 8; c++) {
            // wait for the single producer covering this thread's K-range
            if (s > 0) {
                const unsigned* pf = poll_flag_base + (c * 4 + (seg >> 3)) * 32;
                const unsigned tgt = base + (unsigned)s;
                unsigned v;
                do {
                    asm volatile("ld.global.acquire.gpu.u32 %0, [%1];"
                                 : "=r"(v) : "l"(pf));
                } while ((int)(v - tgt) < 0);
            }
            // issue this thread's 2 staging tasks for chunk c
            {
                const int koff = c * 128 + seg * 4;
                const float* gp0 = hprev + (size_t)(bg + b0t) * hstride + koff;
                const float* gp1 = hprev + (size_t)(bg + b0t + 8) * hstride + koff;
                cp_async16(hs_base + (uint32_t)(b0t * 1024 + koff) * 4u, gp0);
                cp_async16(hs_base + (uint32_t)((b0t + 8) * 1024 + koff) * 4u, gp1);
                asm volatile("cp.async.commit_group;" ::: "memory");
            }
            // compute chunk c-1 while chunk c is in flight
            if (c >= 1) {
                asm volatile("cp.async.wait_group 1;" ::: "memory");
                __syncthreads();
                const int kc = (c - 1) * 128 + lane * 4;
                ulonglong2 w2[8];
#pragma unroll
                for (int f = 0; f < 8; f++)
                    w2[f] = *(const ulonglong2*)&wsm[(fw * 8 + f) * 1024 + kc];
#pragma unroll
                for (int b = 0; b < 8; b++) {
                    ulonglong2 hv = *(const ulonglong2*)&hs[(bw * 8 + b) * 1024 + kc];
#pragma unroll
                    for (int f = 0; f < 8; f++) {
                        fma2(acc[f][b], hv.x, w2[f].x);
                        fma2(acc[f][b], hv.y, w2[f].y);
                    }
                }
            }
        }
        // final chunk
        {
            asm volatile("cp.async.wait_group 0;" ::: "memory");
            __syncthreads();
            const int kc = 7 * 128 + lane * 4;
            ulonglong2 w2[8];
#pragma unroll
            for (int f = 0; f < 8; f++)
                w2[f] = *(const ulonglong2*)&wsm[(fw * 8 + f) * 1024 + kc];
#pragma unroll
            for (int b = 0; b < 8; b++) {
                ulonglong2 hv = *(const ulonglong2*)&hs[(bw * 8 + b) * 1024 + kc];
#pragma unroll
                for (int f = 0; f < 8; f++) {
                    fma2(acc[f][b], hv.x, w2[f].x);
                    fma2(acc[f][b], hv.y, w2[f].y);
                }
            }
        }
        __syncthreads();   // hs reads done; red may alias it

        // ---- reduce 32 lane K-slices; two passes of 32 outputs ----
        float* y_s0 = yp0 + (size_t)s * H_;
        float* y_s1 = yp1 + (size_t)s * H_;
#pragma unroll
        for (int p = 0; p < 2; p++) {
            __syncwarp();
#pragma unroll
            for (int ff = 0; ff < 4; ff++) {
                int f = p * 4 + ff;
#pragma unroll
                for (int b = 0; b < 8; b++)
                    red[w][ff * 8 + b][lane] = pairsum(acc[f][b]);
            }
            __syncwarp();
            float sum = 0.0f;
#pragma unroll
            for (int j = 0; j < 32; j++) sum += red[w][lane][j];

            if (p == 0) {
                float val = tanhf(wx0 + sum + bias0);
                *y_s0 = val;
                if (s == S_ - 1) hlast[(size_t)bgl * H_ + fg0] = val;
            } else {
                float val = tanhf(wx1 + sum + bias1);
                *y_s1 = val;
                if (s == S_ - 1) hlast[(size_t)bgl * H_ + fg1] = val;
            }
        }

        // wx prefetch for next step (overlaps flag propagation)
        if (s < S_ - 1) {
            wx0 = y_s0[H_];
            wx1 = y_s1[H_];
        }

        // publish our slice of y[s]
        __syncthreads();   // all threads' STG of y[s] done; also protects red/hs
        if (tid == 0 && s < S_ - 1) {
            asm volatile("st.global.release.gpu.u32 [%0], %1;"
                         :: "l"(my_flag), "r"(base + (unsigned)s + 1u));
        }
    }
}

// ============================================================================
// Launch: 4 graph nodes. Inputs: x, h, Wih_w, Wih_b, Whh_w, Whh_b.
// Output: y [B,S,H] followed by h_last [B,H].
// ============================================================================
extern "C" void kernel_launch(void* const* d_in, const int* in_sizes, int n_in,
                              void* d_out, int out_size)
{
    const float* x     = (const float*)d_in[0];
    const float* h0    = (const float*)d_in[1];
    const float* Wih_w = (const float*)d_in[2];
    const float* Wih_b = (const float*)d_in[3];
    const float* Whh_w = (const float*)d_in[4];
    const float* Whh_b = (const float*)d_in[5];

    float* y     = (float*)d_out;
    float* hlast = y + (size_t)B_ * S_ * H_;

    const int mma_smem = 2 * STG_BYTES;   // 61440
    cudaFuncSetAttribute(wx_mma, cudaFuncAttributeMaxDynamicSharedMemorySize,
                         mma_smem);
    const int rnn_smem = (32 * 1024 + 16 * 1024) * sizeof(float);  // 196608
    cudaFuncSetAttribute(rnn_persistent,
                         cudaFuncAttributeMaxDynamicSharedMemorySize, rnn_smem);

    cvt_split<<<8192, 256>>>(x, 0, 16777216);      // x: 16M float4
    cvt_split<<<1024, 256>>>(Wih_w, 1, 262144);    // W: 256K float4
    wx_mma<<<dim3(16, 512), 256, mma_smem>>>(Wih_b, y);
    rnn_persistent<<<dim3(32, 4), 256, rnn_smem>>>(h0, Whh_w, Whh_b, y, hlast);
}

// round 10
// speedup vs baseline: 1.2714x; 1.2714x over previous
#include <cuda_runtime.h>
#include <cstdint>

typedef unsigned long long ULL;

#define B_   64
#define S_   1024
#define I_   1024
#define H_   1024
#define SH_  (S_ * H_)   // 1048576

// ---- packed f32x2 helpers ----
__device__ __forceinline__ void fma2(ULL& d, ULL a, ULL b) {
    asm("fma.rn.f32x2 %0, %1, %2, %0;" : "+l"(d) : "l"(a), "l"(b));
}
__device__ __forceinline__ float pairsum(ULL v) {
    union { ULL u; float2 f; } t;
    t.u = v;
    return t.f.x + t.f.y;
}
__device__ __forceinline__ void cp_async16(uint32_t smem_addr, const void* gptr) {
    asm volatile("cp.async.cg.shared.global [%0], [%1], 16;"
                 :: "r"(smem_addr), "l"(gptr));
}
__device__ __forceinline__ uint32_t smem_u32(const void* p) {
    return (uint32_t)__cvta_generic_to_shared(p);
}
// pack: low half = bf16(v0), high half = bf16(v1)
__device__ __forceinline__ uint32_t pack_bf16(float v0, float v1) {
    uint32_t r;
    asm("cvt.rn.bf16x2.f32 %0, %1, %2;" : "=r"(r) : "f"(v1), "f"(v0));
    return r;
}

// ============================================================================
// Static scratch: split-bf16 copies of x and Wih (u32 = 2 packed bf16).
// ============================================================================
__device__ unsigned g_xhi[33554432];   // 64M bf16 = 128 MB
__device__ unsigned g_xlo[33554432];
__device__ unsigned g_whi[524288];     // 1M bf16
__device__ unsigned g_wlo[524288];

// ============================================================================
// Convert fp32 -> (hi, lo) bf16 pairs. which: 0 = x, 1 = W.
// ============================================================================
__global__ void cvt_split(const float* __restrict__ src, int which, int n4)
{
    unsigned* hi = which ? g_whi : g_xhi;
    unsigned* lo = which ? g_wlo : g_xlo;
    int stride = gridDim.x * blockDim.x;
    for (int i = blockIdx.x * blockDim.x + threadIdx.x; i < n4; i += stride) {
        float4 v = ((const float4*)src)[i];
        uint32_t h0 = pack_bf16(v.x, v.y);
        uint32_t h1 = pack_bf16(v.z, v.w);
        float l0 = v.x - __uint_as_float(h0 << 16);
        float l1 = v.y - __uint_as_float(h0 & 0xFFFF0000u);
        float l2 = v.z - __uint_as_float(h1 << 16);
        float l3 = v.w - __uint_as_float(h1 & 0xFFFF0000u);
        hi[2 * i]     = h0;
        hi[2 * i + 1] = h1;
        lo[2 * i]     = pack_bf16(l0, l1);
        lo[2 * i + 1] = pack_bf16(l2, l3);
    }
}

// ============================================================================
// wx_mma: y[m,n] = sum_k x[m,k] * Wih[n,k] + bias[n] via split-bf16 HMMA.
// (unchanged — known good at ~1 ms)
// ============================================================================
#define STG_BYTES 30720
#define A_LO_OFF  10240
#define B_OFF     20480
#define B_LO_OFF  25600

__device__ __forceinline__ void mma_bf16(float& c0, float& c1, float& c2, float& c3,
                                         uint32_t a0, uint32_t a1, uint32_t a2, uint32_t a3,
                                         uint32_t b0, uint32_t b1) {
    asm volatile("mma.sync.aligned.m16n8k16.row.col.f32.bf16.bf16.f32 "
                 "{%0,%1,%2,%3}, {%4,%5,%6,%7}, {%8,%9}, {%0,%1,%2,%3};"
                 : "+f"(c0), "+f"(c1), "+f"(c2), "+f"(c3)
                 : "r"(a0), "r"(a1), "r"(a2), "r"(a3), "r"(b0), "r"(b1));
}

__global__ __launch_bounds__(256, 2)
void wx_mma(const float* __restrict__ bias, float* __restrict__ y)
{
    extern __shared__ __align__(16) char smem[];
    const uint32_t sbase = smem_u32(smem);

    const int tid  = threadIdx.x;
    const int wid  = tid >> 5;
    const int lane = tid & 31;
    const int g    = lane >> 2;
    const int t    = lane & 3;
    const int wm   = wid & 3;
    const int wn   = wid >> 2;
    const int m0   = blockIdx.y * 128;
    const int n0   = blockIdx.x * 64;

    float acc[2][4][4];
#pragma unroll
    for (int mf = 0; mf < 2; mf++)
#pragma unroll
        for (int nf = 0; nf < 4; nf++)
#pragma unroll
            for (int c = 0; c < 4; c++) acc[mf][nf][c] = 0.0f;

    auto issue = [&](int st) {
        const uint32_t d = sbase + (st & 1) * STG_BYTES;
        const int k0 = st * 32;
#pragma unroll
        for (int r = 0; r < 4; r++) {
            int id   = tid + 256 * r;
            int part = id >> 9;
            int rem  = id & 511;
            int row  = rem >> 2;
            int seg  = rem & 3;
            const unsigned* srcb = part ? g_xlo : g_xhi;
            const char* src = (const char*)(srcb +
                ((size_t)(m0 + row) * 1024 + k0) / 2) + seg * 16;
            cp_async16(d + part * A_LO_OFF + row * 80 + seg * 16, src);
        }
#pragma unroll
        for (int r = 0; r < 2; r++) {
            int id   = tid + 256 * r;
            int part = id >> 8;
            int rem  = id & 255;
            int row  = rem >> 2;
            int seg  = rem & 3;
            const unsigned* srcb = part ? g_wlo : g_whi;
            const char* src = (const char*)(srcb +
                ((size_t)(n0 + row) * 1024 + k0) / 2) + seg * 16;
            cp_async16(d + B_OFF + part * 5120 + row * 80 + seg * 16, src);
        }
        asm volatile("cp.async.commit_group;" ::: "memory");
    };

    issue(0);
    for (int i = 0; i < 32; i++) {
        if (i + 1 < 32) {
            issue(i + 1);
            asm volatile("cp.async.wait_group 1;" ::: "memory");
        } else {
            asm volatile("cp.async.wait_group 0;" ::: "memory");
        }
        __syncthreads();

        const char* sm  = smem + (i & 1) * STG_BYTES;
        const char* Ahi = sm;
        const char* Alo = sm + A_LO_OFF;
        const char* Bhi = sm + B_OFF;
        const char* Blo = sm + B_LO_OFF;

#pragma unroll
        for (int ks = 0; ks < 32; ks += 16) {
            const int colb = (ks + t * 2) * 2;
            uint32_t ah[2][4], al[2][4];
#pragma unroll
            for (int mf = 0; mf < 2; mf++) {
                int r0 = (wm * 32 + mf * 16 + g) * 80;
                int r1 = r0 + 8 * 80;
                ah[mf][0] = *(const uint32_t*)(Ahi + r0 + colb);
                ah[mf][1] = *(const uint32_t*)(Ahi + r1 + colb);
                ah[mf][2] = *(const uint32_t*)(Ahi + r0 + colb + 16);
                ah[mf][3] = *(const uint32_t*)(Ahi + r1 + colb + 16);
                al[mf][0] = *(const uint32_t*)(Alo + r0 + colb);
                al[mf][1] = *(const uint32_t*)(Alo + r1 + colb);
                al[mf][2] = *(const uint32_t*)(Alo + r0 + colb + 16);
                al[mf][3] = *(const uint32_t*)(Alo + r1 + colb + 16);
            }
            uint32_t bh[4][2], bl[4][2];
#pragma unroll
            for (int nf = 0; nf < 4; nf++) {
                int nr = (wn * 32 + nf * 8 + g) * 80;
                bh[nf][0] = *(const uint32_t*)(Bhi + nr + colb);
                bh[nf][1] = *(const uint32_t*)(Bhi + nr + colb + 16);
                bl[nf][0] = *(const uint32_t*)(Blo + nr + colb);
                bl[nf][1] = *(const uint32_t*)(Blo + nr + colb + 16);
            }
#pragma unroll
            for (int mf = 0; mf < 2; mf++)
#pragma unroll
                for (int nf = 0; nf < 4; nf++) {
                    float* c = acc[mf][nf];
                    mma_bf16(c[0], c[1], c[2], c[3],
                             ah[mf][0], ah[mf][1], ah[mf][2], ah[mf][3],
                             bh[nf][0], bh[nf][1]);
                    mma_bf16(c[0], c[1], c[2], c[3],
                             al[mf][0], al[mf][1], al[mf][2], al[mf][3],
                             bh[nf][0], bh[nf][1]);
                    mma_bf16(c[0], c[1], c[2], c[3],
                             ah[mf][0], ah[mf][1], ah[mf][2], ah[mf][3],
                             bl[nf][0], bl[nf][1]);
                }
        }
        __syncthreads();
    }

#pragma unroll
    for (int mf = 0; mf < 2; mf++) {
        int m = m0 + wm * 32 + mf * 16 + g;
#pragma unroll
        for (int nf = 0; nf < 4; nf++) {
            int n = n0 + wn * 32 + nf * 8 + t * 2;
            float2 bv = *(const float2*)(bias + n);
            float* c = acc[mf][nf];
            *(float2*)(y + (size_t)m * H_ + n) =
                make_float2(c[0] + bv.x, c[1] + bv.y);
            *(float2*)(y + (size_t)(m + 8) * H_ + n) =
                make_float2(c[2] + bv.x, c[3] + bv.y);
        }
    }
}

// ============================================================================
// Sync structures.
// Entry rendezvous: R8-style full per-bg barrier (fresh gen read inside).
// Per-step: two half-barriers per bg (lo = producers ft0-15 / k<512,
// hi = ft16-31 / k>=512). 16 arrivers each; all 32 CTAs wait. Targets are
// computed from gen0 values read at entry (safe: no flip can precede the
// entry rendezvous, which needs every CTA's arrival).
// ============================================================================
__device__ unsigned g_cnt[4 * 32];          // rendezvous counters, per bg
__device__ unsigned g_gen[4 * 32];
__device__ unsigned g_hcnt[8 * 32];         // (bg*2+half)*32
__device__ unsigned g_hgen[8 * 32];

__device__ __forceinline__ void rendezvous(int bg, unsigned nb) {
    __syncthreads();
    if (threadIdx.x == 0) {
        unsigned* cnt = &g_cnt[bg * 32];
        unsigned* gen = &g_gen[bg * 32];
        unsigned g;
        asm volatile("ld.global.acquire.gpu.u32 %0, [%1];" : "=r"(g) : "l"(gen));
        unsigned prev;
        asm volatile("atom.global.acq_rel.gpu.add.u32 %0, [%1], %2;"
                     : "=r"(prev) : "l"(cnt), "r"(1u));
        if (prev == nb - 1) {
            asm volatile("st.global.relaxed.gpu.u32 [%0], %1;" :: "l"(cnt), "r"(0u));
            asm volatile("st.global.release.gpu.u32 [%0], %1;" :: "l"(gen), "r"(g + 1u));
        } else {
            unsigned cur;
            do {
                asm volatile("ld.global.acquire.gpu.u32 %0, [%1];" : "=r"(cur) : "l"(gen));
            } while (cur == g);
        }
    }
    __syncthreads();
}

__device__ __forceinline__ void poll_ge(const unsigned* p, unsigned tgt) {
    unsigned v;
    do {
        asm volatile("ld.global.acquire.gpu.u32 %0, [%1];" : "=r"(v) : "l"(p));
    } while ((int)(v - tgt) < 0);
}

__device__ __forceinline__ void half_arrive(unsigned* cnt, unsigned* gen, unsigned tgt) {
    unsigned prev;
    asm volatile("atom.global.acq_rel.gpu.add.u32 %0, [%1], %2;"
                 : "=r"(prev) : "l"(cnt), "r"(1u));
    if (prev == 15u) {
        asm volatile("st.global.relaxed.gpu.u32 [%0], %1;" :: "l"(cnt), "r"(0u));
        asm volatile("st.global.release.gpu.u32 [%0], %1;" :: "l"(gen), "r"(tgt));
    }
}

// ============================================================================
// Persistent recurrence: R8 pipeline + half-barrier dataflow.
// smem: wsm 32x1024 fp32 (128KB) + hs 16x1024 fp32 (64KB; reduce scratch
// [8][32][36] aliases hs after compute).
// Grid (32 ftiles) x (4 bgroups), 256 thr, 1 CTA/SM.
// ============================================================================
__global__ __launch_bounds__(256, 1)
void rnn_persistent(const float* __restrict__ h0,
                    const float* __restrict__ Whh,
                    const float* __restrict__ bias,
                    float* __restrict__ y,
                    float* __restrict__ hlast)
{
    extern __shared__ float smemf[];
    float* wsm = smemf;
    float* hs  = smemf + 32 * 1024;
    float (*red)[32][36] = (float (*)[32][36])hs;   // 36864 B, aliases hs
    __shared__ unsigned sh_g0[2];

    const int tid  = threadIdx.x;
    const int w    = tid >> 5;
    const int lane = tid & 31;
    const int fw   = w & 3;
    const int bw   = w >> 2;
    const int ft_id = blockIdx.x;          // 0..31
    const int bg_id = blockIdx.y;          // 0..3
    const int ftile = ft_id * 32;
    const int bg    = bg_id * 16;
    const int myhalf = ft_id >> 4;         // 0: lo, 1: hi

    unsigned* lo_gen = &g_hgen[(bg_id * 2 + 0) * 32];
    unsigned* hi_gen = &g_hgen[(bg_id * 2 + 1) * 32];
    unsigned* my_cnt = &g_hcnt[(bg_id * 2 + myhalf) * 32];
    unsigned* my_gen = &g_hgen[(bg_id * 2 + myhalf) * 32];

    // read gen0 for both halves BEFORE the rendezvous (no flip can precede it)
    if (tid == 0) {
        unsigned a, b;
        asm volatile("ld.global.relaxed.gpu.u32 %0, [%1];" : "=r"(a) : "l"(lo_gen));
        asm volatile("ld.global.relaxed.gpu.u32 %0, [%1];" : "=r"(b) : "l"(hi_gen));
        sh_g0[0] = a;
        sh_g0[1] = b;
    }

    // ---- one-time: Whh slice into smem ----
#pragma unroll 4
    for (int r = 0; r < 32; r++) {
        int slot = r * 256 + tid;
        int f = slot >> 8;
        int c = (slot & 255) * 4;
        *(float4*)&wsm[f * 1024 + c] =
            *(const float4*)(Whh + (size_t)(ftile + f) * H_ + c);
    }

    const int fl  = lane >> 3;
    const int bl  = lane & 7;
    const int bgl = bg + bw * 8 + bl;
    const int fg0 = ftile + fw * 8 + 0 * 4 + fl;
    const int fg1 = ftile + fw * 8 + 1 * 4 + fl;
    float bias0 = bias[fg0];
    float bias1 = bias[fg1];
    float* yp0 = y + (size_t)bgl * SH_ + fg0;
    float* yp1 = y + (size_t)bgl * SH_ + fg1;

    const uint32_t hs_base = smem_u32(hs);

    float wx0 = yp0[0];
    float wx1 = yp1[0];

    rendezvous(bg_id, 32);                 // anchors gen0; also covers wsm fill
    const unsigned g0lo = sh_g0[0];
    const unsigned g0hi = sh_g0[1];
    const unsigned g0my = myhalf ? g0hi : g0lo;

    for (int s = 0; s < S_; s++) {
        const float* hprev = (s == 0) ? h0 : (y + (size_t)(s - 1) * H_);
        const int hstride  = (s == 0) ? H_ : SH_;

        // ---- staging helper: chunk c = k range [256c, 256c+256) ----
        auto stage = [&](int c) {
#pragma unroll
            for (int r = 0; r < 4; r++) {
                int idx = r * 256 + tid;
                int b   = idx >> 6;
                int c4  = (idx & 63) << 2;
                const float* gp = hprev + (size_t)(bg + b) * hstride + c * 256 + c4;
                cp_async16(hs_base + (uint32_t)(b * 1024 + c * 256 + c4) * 4u, gp);
            }
            asm volatile("cp.async.commit_group;" ::: "memory");
        };

        ULL acc[8][8];
#pragma unroll
        for (int f = 0; f < 8; f++)
#pragma unroll
            for (int b = 0; b < 8; b++) acc[f][b] = 0ull;

        auto compute = [&](int c) {
#pragma unroll
            for (int half = 0; half < 2; half++) {
                const int kc = c * 256 + half * 128 + lane * 4;
                ulonglong2 w2[8];
#pragma unroll
                for (int f = 0; f < 8; f++)
                    w2[f] = *(const ulonglong2*)&wsm[(fw * 8 + f) * 1024 + kc];
#pragma unroll
                for (int b = 0; b < 8; b++) {
                    ulonglong2 hv = *(const ulonglong2*)&hs[(bw * 8 + b) * 1024 + kc];
#pragma unroll
                    for (int f = 0; f < 8; f++) {
                        fma2(acc[f][b], hv.x, w2[f].x);
                        fma2(acc[f][b], hv.y, w2[f].y);
                    }
                }
            }
        };

        // ---- pipeline: wait lo -> stage c0,c1 -> compute c0 -> wait hi ->
        //      stage c2,c3 -> compute c1,c2,c3 ----
        if (s > 0) {
            if (tid == 0) poll_ge(lo_gen, g0lo + (unsigned)s);
            __syncthreads();
        }
        stage(0);
        stage(1);
        asm volatile("cp.async.wait_group 1;" ::: "memory");
        __syncthreads();
        compute(0);
        if (s > 0) {
            if (tid == 0) poll_ge(hi_gen, g0hi + (unsigned)s);
            __syncthreads();
        }
        stage(2);
        stage(3);
        asm volatile("cp.async.wait_group 2;" ::: "memory");
        __syncthreads();
        compute(1);
        asm volatile("cp.async.wait_group 1;" ::: "memory");
        __syncthreads();
        compute(2);
        asm volatile("cp.async.wait_group 0;" ::: "memory");
        __syncthreads();
        compute(3);
        __syncthreads();   // hs reads done; red may alias it

        // ---- reduce 32 lane K-slices; two passes of 32 outputs ----
        float* y_s0 = yp0 + (size_t)s * H_;
        float* y_s1 = yp1 + (size_t)s * H_;
#pragma unroll
        for (int p = 0; p < 2; p++) {
            __syncwarp();
#pragma unroll
            for (int ff = 0; ff < 4; ff++) {
                int f = p * 4 + ff;
#pragma unroll
                for (int b = 0; b < 8; b++)
                    red[w][ff * 8 + b][lane] = pairsum(acc[f][b]);
            }
            __syncwarp();
            const float4* row = (const float4*)red[w][lane];
            float4 v = row[0];
#pragma unroll
            for (int j = 1; j < 8; j++) {
                float4 u = row[j];
                v.x += u.x; v.y += u.y; v.z += u.z; v.w += u.w;
            }
            float sum = (v.x + v.y) + (v.z + v.w);

            if (p == 0) {
                float val = tanhf(wx0 + sum + bias0);
                *y_s0 = val;
                if (s == S_ - 1) hlast[(size_t)bgl * H_ + fg0] = val;
            } else {
                float val = tanhf(wx1 + sum + bias1);
                *y_s1 = val;
                if (s == S_ - 1) hlast[(size_t)bgl * H_ + fg1] = val;
            }
        }

        // wx prefetch for next step
        if (s < S_ - 1) {
            wx0 = y_s0[H_];
            wx1 = y_s1[H_];
        }

        __syncthreads();   // all y[s] stores done
        if (tid == 0 && s < S_ - 1)
            half_arrive(my_cnt, my_gen, g0my + (unsigned)s + 1u);
    }
}

// ============================================================================
// Launch: 4 graph nodes. Inputs: x, h, Wih_w, Wih_b, Whh_w, Whh_b.
// Output: y [B,S,H] followed by h_last [B,H].
// ============================================================================
extern "C" void kernel_launch(void* const* d_in, const int* in_sizes, int n_in,
                              void* d_out, int out_size)
{
    const float* x     = (const float*)d_in[0];
    const float* h0    = (const float*)d_in[1];
    const float* Wih_w = (const float*)d_in[2];
    const float* Wih_b = (const float*)d_in[3];
    const float* Whh_w = (const float*)d_in[4];
    const float* Whh_b = (const float*)d_in[5];

    float* y     = (float*)d_out;
    float* hlast = y + (size_t)B_ * S_ * H_;

    const int mma_smem = 2 * STG_BYTES;   // 61440
    cudaFuncSetAttribute(wx_mma, cudaFuncAttributeMaxDynamicSharedMemorySize,
                         mma_smem);
    const int rnn_smem = (32 * 1024 + 16 * 1024) * sizeof(float);  // 196608
    cudaFuncSetAttribute(rnn_persistent,
                         cudaFuncAttributeMaxDynamicSharedMemorySize, rnn_smem);

    cvt_split<<<8192, 256>>>(x, 0, 16777216);      // x: 16M float4
    cvt_split<<<1024, 256>>>(Wih_w, 1, 262144);    // W: 256K float4
    wx_mma<<<dim3(16, 512), 256, mma_smem>>>(Wih_b, y);
    rnn_persistent<<<dim3(32, 4), 256, rnn_smem>>>(h0, Whh_w, Whh_b, y, hlast);
}

// round 12
// speedup vs baseline: 1.4363x; 1.1297x over previous
#include <cuda_runtime.h>
#include <cstdint>

typedef unsigned long long ULL;

#define B_   64
#define S_   1024
#define I_   1024
#define H_   1024
#define SH_  (S_ * H_)   // 1048576

// ---- helpers ----
__device__ __forceinline__ void cp_async16(uint32_t smem_addr, const void* gptr) {
    asm volatile("cp.async.cg.shared.global [%0], [%1], 16;"
                 :: "r"(smem_addr), "l"(gptr));
}
__device__ __forceinline__ uint32_t smem_u32(const void* p) {
    return (uint32_t)__cvta_generic_to_shared(p);
}
// pack: low half = bf16(v0), high half = bf16(v1)
__device__ __forceinline__ uint32_t pack_bf16(float v0, float v1) {
    uint32_t r;
    asm("cvt.rn.bf16x2.f32 %0, %1, %2;" : "=r"(r) : "f"(v1), "f"(v0));
    return r;
}
__device__ __forceinline__ void ldsm_x4(uint32_t& r0, uint32_t& r1,
                                        uint32_t& r2, uint32_t& r3, uint32_t a) {
    asm volatile("ldmatrix.sync.aligned.m8n8.x4.shared.b16 {%0,%1,%2,%3}, [%4];"
                 : "=r"(r0), "=r"(r1), "=r"(r2), "=r"(r3) : "r"(a));
}
__device__ __forceinline__ void ldsm_x2(uint32_t& r0, uint32_t& r1, uint32_t a) {
    asm volatile("ldmatrix.sync.aligned.m8n8.x2.shared.b16 {%0,%1}, [%2];"
                 : "=r"(r0), "=r"(r1) : "r"(a));
}
__device__ __forceinline__ void mma_bf16(float& c0, float& c1, float& c2, float& c3,
                                         uint32_t a0, uint32_t a1, uint32_t a2, uint32_t a3,
                                         uint32_t b0, uint32_t b1) {
    asm volatile("mma.sync.aligned.m16n8k16.row.col.f32.bf16.bf16.f32 "
                 "{%0,%1,%2,%3}, {%4,%5,%6,%7}, {%8,%9}, {%0,%1,%2,%3};"
                 : "+f"(c0), "+f"(c1), "+f"(c2), "+f"(c3)
                 : "r"(a0), "r"(a1), "r"(a2), "r"(a3), "r"(b0), "r"(b1));
}

// ============================================================================
// Static scratch.
// ============================================================================
__device__ unsigned g_xhi[33554432];   // x split-bf16 (wx path)
__device__ unsigned g_xlo[33554432];
__device__ unsigned g_whi[524288];     // Wih split-bf16
__device__ unsigned g_wlo[524288];
__device__ unsigned g_hb[2][2][32768]; // h state, [parity][hi/lo][64 rows x 512 u32]

// ============================================================================
// Convert fp32 -> (hi, lo) bf16 pairs. which: 0 = x, 1 = W. (wx path)
// ============================================================================
__global__ void cvt_split(const float* __restrict__ src, int which, int n4)
{
    unsigned* hi = which ? g_whi : g_xhi;
    unsigned* lo = which ? g_wlo : g_xlo;
    int stride = gridDim.x * blockDim.x;
    for (int i = blockIdx.x * blockDim.x + threadIdx.x; i < n4; i += stride) {
        float4 v = ((const float4*)src)[i];
        uint32_t h0 = pack_bf16(v.x, v.y);
        uint32_t h1 = pack_bf16(v.z, v.w);
        float l0 = v.x - __uint_as_float(h0 << 16);
        float l1 = v.y - __uint_as_float(h0 & 0xFFFF0000u);
        float l2 = v.z - __uint_as_float(h1 << 16);
        float l3 = v.w - __uint_as_float(h1 & 0xFFFF0000u);
        hi[2 * i]     = h0;
        hi[2 * i + 1] = h1;
        lo[2 * i]     = pack_bf16(l0, l1);
        lo[2 * i + 1] = pack_bf16(l2, l3);
    }
}

// ============================================================================
// wx_mma (unchanged, known good ~1 ms).
// ============================================================================
#define STG_BYTES 30720
#define A_LO_OFF  10240
#define B_OFF     20480
#define B_LO_OFF  25600

__global__ __launch_bounds__(256, 2)
void wx_mma(const float* __restrict__ bias, float* __restrict__ y)
{
    extern __shared__ __align__(16) char smem[];
    const uint32_t sbase = smem_u32(smem);

    const int tid  = threadIdx.x;
    const int wid  = tid >> 5;
    const int lane = tid & 31;
    const int g    = lane >> 2;
    const int t    = lane & 3;
    const int wm   = wid & 3;
    const int wn   = wid >> 2;
    const int m0   = blockIdx.y * 128;
    const int n0   = blockIdx.x * 64;

    float acc[2][4][4];
#pragma unroll
    for (int mf = 0; mf < 2; mf++)
#pragma unroll
        for (int nf = 0; nf < 4; nf++)
#pragma unroll
            for (int c = 0; c < 4; c++) acc[mf][nf][c] = 0.0f;

    auto issue = [&](int st) {
        const uint32_t d = sbase + (st & 1) * STG_BYTES;
        const int k0 = st * 32;
#pragma unroll
        for (int r = 0; r < 4; r++) {
            int id   = tid + 256 * r;
            int part = id >> 9;
            int rem  = id & 511;
            int row  = rem >> 2;
            int seg  = rem & 3;
            const unsigned* srcb = part ? g_xlo : g_xhi;
            const char* src = (const char*)(srcb +
                ((size_t)(m0 + row) * 1024 + k0) / 2) + seg * 16;
            cp_async16(d + part * A_LO_OFF + row * 80 + seg * 16, src);
        }
#pragma unroll
        for (int r = 0; r < 2; r++) {
            int id   = tid + 256 * r;
            int part = id >> 8;
            int rem  = id & 255;
            int row  = rem >> 2;
            int seg  = rem & 3;
            const unsigned* srcb = part ? g_wlo : g_whi;
            const char* src = (const char*)(srcb +
                ((size_t)(n0 + row) * 1024 + k0) / 2) + seg * 16;
            cp_async16(d + B_OFF + part * 5120 + row * 80 + seg * 16, src);
        }
        asm volatile("cp.async.commit_group;" ::: "memory");
    };

    issue(0);
    for (int i = 0; i < 32; i++) {
        if (i + 1 < 32) {
            issue(i + 1);
            asm volatile("cp.async.wait_group 1;" ::: "memory");
        } else {
            asm volatile("cp.async.wait_group 0;" ::: "memory");
        }
        __syncthreads();

        const char* sm  = smem + (i & 1) * STG_BYTES;
        const char* Ahi = sm;
        const char* Alo = sm + A_LO_OFF;
        const char* Bhi = sm + B_OFF;
        const char* Blo = sm + B_LO_OFF;

#pragma unroll
        for (int ks = 0; ks < 32; ks += 16) {
            const int colb = (ks + t * 2) * 2;
            uint32_t ah[2][4], al[2][4];
#pragma unroll
            for (int mf = 0; mf < 2; mf++) {
                int r0 = (wm * 32 + mf * 16 + g) * 80;
                int r1 = r0 + 8 * 80;
                ah[mf][0] = *(const uint32_t*)(Ahi + r0 + colb);
                ah[mf][1] = *(const uint32_t*)(Ahi + r1 + colb);
                ah[mf][2] = *(const uint32_t*)(Ahi + r0 + colb + 16);
                ah[mf][3] = *(const uint32_t*)(Ahi + r1 + colb + 16);
                al[mf][0] = *(const uint32_t*)(Alo + r0 + colb);
                al[mf][1] = *(const uint32_t*)(Alo + r1 + colb);
                al[mf][2] = *(const uint32_t*)(Alo + r0 + colb + 16);
                al[mf][3] = *(const uint32_t*)(Alo + r1 + colb + 16);
            }
            uint32_t bh[4][2], bl[4][2];
#pragma unroll
            for (int nf = 0; nf < 4; nf++) {
                int nr = (wn * 32 + nf * 8 + g) * 80;
                bh[nf][0] = *(const uint32_t*)(Bhi + nr + colb);
                bh[nf][1] = *(const uint32_t*)(Bhi + nr + colb + 16);
                bl[nf][0] = *(const uint32_t*)(Blo + nr + colb);
                bl[nf][1] = *(const uint32_t*)(Blo + nr + colb + 16);
            }
#pragma unroll
            for (int mf = 0; mf < 2; mf++)
#pragma unroll
                for (int nf = 0; nf < 4; nf++) {
                    float* c = acc[mf][nf];
                    mma_bf16(c[0], c[1], c[2], c[3],
                             ah[mf][0], ah[mf][1], ah[mf][2], ah[mf][3],
                             bh[nf][0], bh[nf][1]);
                    mma_bf16(c[0], c[1], c[2], c[3],
                             al[mf][0], al[mf][1], al[mf][2], al[mf][3],
                             bh[nf][0], bh[nf][1]);
                    mma_bf16(c[0], c[1], c[2], c[3],
                             ah[mf][0], ah[mf][1], ah[mf][2], ah[mf][3],
                             bl[nf][0], bl[nf][1]);
                }
        }
        __syncthreads();
    }

#pragma unroll
    for (int mf = 0; mf < 2; mf++) {
        int m = m0 + wm * 32 + mf * 16 + g;
#pragma unroll
        for (int nf = 0; nf < 4; nf++) {
            int n = n0 + wn * 32 + nf * 8 + t * 2;
            float2 bv = *(const float2*)(bias + n);
            float* c = acc[mf][nf];
            *(float2*)(y + (size_t)m * H_ + n) =
                make_float2(c[0] + bv.x, c[1] + bv.y);
            *(float2*)(y + (size_t)(m + 8) * H_ + n) =
                make_float2(c[2] + bv.x, c[3] + bv.y);
        }
    }
}

// ============================================================================
// R8's full per-bg barrier (known good). 4 independent 32-CTA barriers.
// ============================================================================
__device__ unsigned g_cnt[4 * 32];
__device__ unsigned g_gen[4 * 32];

__device__ __forceinline__ void group_barrier(int bg, unsigned nb) {
    __syncthreads();
    if (threadIdx.x == 0) {
        unsigned* cnt = &g_cnt[bg * 32];
        unsigned* gen = &g_gen[bg * 32];
        unsigned g;
        asm volatile("ld.global.acquire.gpu.u32 %0, [%1];" : "=r"(g) : "l"(gen));
        unsigned prev;
        asm volatile("atom.global.acq_rel.gpu.add.u32 %0, [%1], %2;"
                     : "=r"(prev) : "l"(cnt), "r"(1u));
        if (prev == nb - 1) {
            asm volatile("st.global.relaxed.gpu.u32 [%0], %1;" :: "l"(cnt), "r"(0u));
            asm volatile("st.global.release.gpu.u32 [%0], %1;" :: "l"(gen), "r"(g + 1u));
        } else {
            unsigned cur;
            do {
                asm volatile("ld.global.acquire.gpu.u32 %0, [%1];" : "=r"(cur) : "l"(gen));
            } while (cur == g);
        }
    }
    __syncthreads();
}

// ============================================================================
// Persistent recurrence via split-bf16 HMMA.
// Per CTA: C[16 batch][32 feat] += h[16][1024] * Whh_slice[32][1024]^T.
// smem (bytes): WHI 0 (32x2064), WLO 66048, HHI 132096 (16x2064),
//               HLO 165120, RED 198144 (4x16x8 fp32 x2... 2KB). Total 200192.
// Warp w: nf = w&3 (8 features), kw = w>>2 (K half via chunks 2kw,2kw+1).
// 3-MMA split: hi*hi + lo*hi + hi*lo, fp32 accum.
// h state: g_hb[parity][hi/lo], produced as packed bf16 by the writeback.
// ============================================================================
#define WHI_OFF 0
#define WLO_OFF 66048
#define HHI_OFF 132096
#define HLO_OFF 165120
#define RED_OFF 198144
#define RNN_SMEM 200192

__global__ __launch_bounds__(256, 1)
void rnn_persistent(const float* __restrict__ h0,
                    const float* __restrict__ Whh,
                    const float* __restrict__ bias,
                    float* __restrict__ y,
                    float* __restrict__ hlast)
{
    extern __shared__ __align__(16) char smem[];
    const uint32_t sb = smem_u32(smem);

    const int tid  = threadIdx.x;
    const int w    = tid >> 5;
    const int lane = tid & 31;
    const int nf   = w & 3;
    const int kw   = w >> 2;
    const int ft_id = blockIdx.x;
    const int bg_id = blockIdx.y;
    const int ftile = ft_id * 32;
    const int bg    = bg_id * 16;

    // ---- one-time: Whh slice -> smem split bf16, 2064B padded rows ----
    {
        const int r = tid >> 3;            // 0..31 feature row
        const int part = tid & 7;          // k segment of 128
        const float* src = Whh + (size_t)(ftile + r) * H_ + part * 128;
        char* dhi = smem + WHI_OFF + r * 2064 + part * 256;
        char* dlo = smem + WLO_OFF + r * 2064 + part * 256;
#pragma unroll
        for (int u = 0; u < 32; u++) {
            float4 v = *(const float4*)(src + u * 4);
            uint32_t h0p = pack_bf16(v.x, v.y);
            uint32_t h1p = pack_bf16(v.z, v.w);
            float l0 = v.x - __uint_as_float(h0p << 16);
            float l1 = v.y - __uint_as_float(h0p & 0xFFFF0000u);
            float l2 = v.z - __uint_as_float(h1p << 16);
            float l3 = v.w - __uint_as_float(h1p & 0xFFFF0000u);
            *(uint2*)(dhi + u * 8) = make_uint2(h0p, h1p);
            *(uint2*)(dlo + u * 8) = make_uint2(pack_bf16(l0, l1), pack_bf16(l2, l3));
        }
    }

    // ---- one-time: ft0 CTA converts h0 (its bg's 16 rows) into g_hb[0] ----
    if (ft_id == 0) {
        const int r = tid >> 4;            // 0..15
        const int part = tid & 15;         // 64 floats each
        const float* src = h0 + (size_t)(bg + r) * H_ + part * 64;
        unsigned* dhi = &g_hb[0][0][(bg + r) * 512 + part * 32];
        unsigned* dlo = &g_hb[0][1][(bg + r) * 512 + part * 32];
#pragma unroll
        for (int u = 0; u < 16; u++) {
            float4 v = *(const float4*)(src + u * 4);
            uint32_t h0p = pack_bf16(v.x, v.y);
            uint32_t h1p = pack_bf16(v.z, v.w);
            float l0 = v.x - __uint_as_float(h0p << 16);
            float l1 = v.y - __uint_as_float(h0p & 0xFFFF0000u);
            float l2 = v.z - __uint_as_float(h1p << 16);
            float l3 = v.w - __uint_as_float(h1p & 0xFFFF0000u);
            *(uint2*)(dhi + u * 2) = make_uint2(h0p, h1p);
            *(uint2*)(dlo + u * 2) = make_uint2(pack_bf16(l0, l1), pack_bf16(l2, l3));
        }
    }

    // ---- output mapping (kw==0 warps do writeback) ----
    const int mq = lane >> 2;              // 0..7
    const int q  = lane & 3;
    const int fgn  = ftile + nf * 8 + q * 2;
    const int rowA = bg + mq;
    const int rowB = bg + mq + 8;
    float2 bias2 = *(const float2*)(bias + fgn);
    float* yA = y + (size_t)rowA * SH_ + fgn;
    float* yB = y + (size_t)rowB * SH_ + fgn;
    float2 wxA = *(float2*)yA;
    float2 wxB = *(float2*)yB;

    // ---- ldmatrix base addresses ----
    const uint32_t aHiB = sb + HHI_OFF + (uint32_t)(lane & 15) * 2064 +
                          (uint32_t)((lane >> 4) << 4);
    const uint32_t aLoB = aHiB + (HLO_OFF - HHI_OFF);
    const int bl = lane & 15;
    const uint32_t bHiB = sb + WHI_OFF +
                          (uint32_t)(nf * 8 + (bl & 7)) * 2064 +
                          (uint32_t)(((bl >> 3) & 1) << 4);
    const uint32_t bLoB = bHiB + (WLO_OFF - WHI_OFF);

    group_barrier(bg_id, 32);   // entry: h0 conversion visible group-wide

    for (int s = 0; s < S_; s++) {
        const int p = s & 1;

        // ---- stage h (hi+lo bf16) in 4 commit groups of 256 K ----
#pragma unroll
        for (int c = 0; c < 4; c++) {
#pragma unroll
            for (int r = 0; r < 4; r++) {
                int id    = tid + 256 * r;        // 0..1023
                int split = id >> 9;
                int rem   = id & 511;
                int row   = rem >> 5;             // 0..15
                int seg   = rem & 31;             // 0..31
                const char* src = (const char*)g_hb[p][split] +
                                  (size_t)(bg + row) * 2048 + c * 512 + seg * 16;
                cp_async16(sb + (split ? HLO_OFF : HHI_OFF) +
                           (uint32_t)(row * 2064 + c * 512 + seg * 16), src);
            }
            asm volatile("cp.async.commit_group;" ::: "memory");
        }

        float c0 = 0.f, c1 = 0.f, c2 = 0.f, c3 = 0.f;

#pragma unroll
        for (int c = 0; c < 4; c++) {
            if      (c == 0) asm volatile("cp.async.wait_group 3;" ::: "memory");
            else if (c == 1) asm volatile("cp.async.wait_group 2;" ::: "memory");
            else if (c == 2) asm volatile("cp.async.wait_group 1;" ::: "memory");
            else             asm volatile("cp.async.wait_group 0;" ::: "memory");
            __syncthreads();

            if ((c >> 1) == kw) {
                const int kc = c * 256;
#pragma unroll 4
                for (int i = 0; i < 16; i++) {
                    const uint32_t kb = (uint32_t)(kc + i * 16) * 2;
                    uint32_t ah0, ah1, ah2, ah3, al0, al1, al2, al3;
                    uint32_t bh0, bh1, blo0, blo1;
                    ldsm_x4(ah0, ah1, ah2, ah3, aHiB + kb);
                    ldsm_x4(al0, al1, al2, al3, aLoB + kb);
                    ldsm_x2(bh0, bh1, bHiB + kb);
                    ldsm_x2(blo0, blo1, bLoB + kb);
                    mma_bf16(c0, c1, c2, c3, ah0, ah1, ah2, ah3, bh0, bh1);
                    mma_bf16(c0, c1, c2, c3, al0, al1, al2, al3, bh0, bh1);
                    mma_bf16(c0, c1, c2, c3, ah0, ah1, ah2, ah3, blo0, blo1);
                }
            }
        }

        // ---- cross-K reduce (2 partials) + writeback ----
        float2* rp = (float2*)(smem + RED_OFF);
        if (kw == 1) {
            rp[(nf * 16 + mq) * 4 + q]     = make_float2(c0, c1);
            rp[(nf * 16 + mq + 8) * 4 + q] = make_float2(c2, c3);
        }
        __syncthreads();
        if (kw == 0) {
            float2 o0 = rp[(nf * 16 + mq) * 4 + q];
            float2 o1 = rp[(nf * 16 + mq + 8) * 4 + q];
            float v00 = tanhf(wxA.x + c0 + o0.x + bias2.x);
            float v01 = tanhf(wxA.y + c1 + o0.y + bias2.y);
            float v10 = tanhf(wxB.x + c2 + o1.x + bias2.x);
            float v11 = tanhf(wxB.y + c3 + o1.y + bias2.y);

            float* ysA = yA + (size_t)s * H_;
            float* ysB = yB + (size_t)s * H_;
            *(float2*)ysA = make_float2(v00, v01);
            *(float2*)ysB = make_float2(v10, v11);

            // split-bf16 h state for next step
            const int p1 = (s + 1) & 1;
            uint32_t hpA = pack_bf16(v00, v01);
            float lA0 = v00 - __uint_as_float(hpA << 16);
            float lA1 = v01 - __uint_as_float(hpA & 0xFFFF0000u);
            uint32_t hpB = pack_bf16(v10, v11);
            float lB0 = v10 - __uint_as_float(hpB << 16);
            float lB1 = v11 - __uint_as_float(hpB & 0xFFFF0000u);
            g_hb[p1][0][rowA * 512 + (fgn >> 1)] = hpA;
            g_hb[p1][1][rowA * 512 + (fgn >> 1)] = pack_bf16(lA0, lA1);
            g_hb[p1][0][rowB * 512 + (fgn >> 1)] = hpB;
            g_hb[p1][1][rowB * 512 + (fgn >> 1)] = pack_bf16(lB0, lB1);

            if (s == S_ - 1) {
                *(float2*)(hlast + (size_t)rowA * H_ + fgn) = make_float2(v00, v01);
                *(float2*)(hlast + (size_t)rowB * H_ + fgn) = make_float2(v10, v11);
            } else {
                wxA = *(float2*)(ysA + H_);
                wxB = *(float2*)(ysB + H_);
            }
        }

        if (s < S_ - 1) group_barrier(bg_id, 32);
    }
}

// ============================================================================
// Launch: 4 graph nodes. Inputs: x, h, Wih_w, Wih_b, Whh_w, Whh_b.
// Output: y [B,S,H] followed by h_last [B,H].
// ============================================================================
extern "C" void kernel_launch(void* const* d_in, const int* in_sizes, int n_in,
                              void* d_out, int out_size)
{
    const float* x     = (const float*)d_in[0];
    const float* h0    = (const float*)d_in[1];
    const float* Wih_w = (const float*)d_in[2];
    const float* Wih_b = (const float*)d_in[3];
    const float* Whh_w = (const float*)d_in[4];
    const float* Whh_b = (const float*)d_in[5];

    float* y     = (float*)d_out;
    float* hlast = y + (size_t)B_ * S_ * H_;

    const int mma_smem = 2 * STG_BYTES;   // 61440
    cudaFuncSetAttribute(wx_mma, cudaFuncAttributeMaxDynamicSharedMemorySize,
                         mma_smem);
    cudaFuncSetAttribute(rnn_persistent,
                         cudaFuncAttributeMaxDynamicSharedMemorySize, RNN_SMEM);

    cvt_split<<<8192, 256>>>(x, 0, 16777216);      // x: 16M float4
    cvt_split<<<1024, 256>>>(Wih_w, 1, 262144);    // W: 256K float4
    wx_mma<<<dim3(16, 512), 256, mma_smem>>>(Wih_b, y);
    rnn_persistent<<<dim3(32, 4), 256, RNN_SMEM>>>(h0, Whh_w, Whh_b, y, hlast);
}

// round 13
// speedup vs baseline: 1.6741x; 1.1656x over previous
#include <cuda_runtime.h>
#include <cstdint>

typedef unsigned long long ULL;

#define B_   64
#define S_   1024
#define I_   1024
#define H_   1024
#define SH_  (S_ * H_)   // 1048576

// ---- helpers ----
__device__ __forceinline__ void cp_async16(uint32_t smem_addr, const void* gptr) {
    asm volatile("cp.async.cg.shared.global [%0], [%1], 16;"
                 :: "r"(smem_addr), "l"(gptr));
}
__device__ __forceinline__ uint32_t smem_u32(const void* p) {
    return (uint32_t)__cvta_generic_to_shared(p);
}
// pack: low half = bf16(v0), high half = bf16(v1)
__device__ __forceinline__ uint32_t pack_bf16(float v0, float v1) {
    uint32_t r;
    asm("cvt.rn.bf16x2.f32 %0, %1, %2;" : "=r"(r) : "f"(v1), "f"(v0));
    return r;
}
__device__ __forceinline__ void ldsm_x4(uint32_t& r0, uint32_t& r1,
                                        uint32_t& r2, uint32_t& r3, uint32_t a) {
    asm volatile("ldmatrix.sync.aligned.m8n8.x4.shared.b16 {%0,%1,%2,%3}, [%4];"
                 : "=r"(r0), "=r"(r1), "=r"(r2), "=r"(r3) : "r"(a));
}
__device__ __forceinline__ void ldsm_x2(uint32_t& r0, uint32_t& r1, uint32_t a) {
    asm volatile("ldmatrix.sync.aligned.m8n8.x2.shared.b16 {%0,%1}, [%2];"
                 : "=r"(r0), "=r"(r1) : "r"(a));
}
__device__ __forceinline__ void mma_bf16(float& c0, float& c1, float& c2, float& c3,
                                         uint32_t a0, uint32_t a1, uint32_t a2, uint32_t a3,
                                         uint32_t b0, uint32_t b1) {
    asm volatile("mma.sync.aligned.m16n8k16.row.col.f32.bf16.bf16.f32 "
                 "{%0,%1,%2,%3}, {%4,%5,%6,%7}, {%8,%9}, {%0,%1,%2,%3};"
                 : "+f"(c0), "+f"(c1), "+f"(c2), "+f"(c3)
                 : "r"(a0), "r"(a1), "r"(a2), "r"(a3), "r"(b0), "r"(b1));
}

// ============================================================================
// Static scratch.
// ============================================================================
__device__ unsigned g_xhi[33554432];   // x split-bf16 (wx path)
__device__ unsigned g_xlo[33554432];
__device__ unsigned g_whi[524288];     // Wih split-bf16
__device__ unsigned g_wlo[524288];
__device__ unsigned g_hb[2][2][32768]; // h state, [parity][hi/lo][64 rows x 512 u32]

// ============================================================================
// Convert fp32 -> (hi, lo) bf16 pairs. which: 0 = x, 1 = W. (wx path)
// ============================================================================
__global__ void cvt_split(const float* __restrict__ src, int which, int n4)
{
    unsigned* hi = which ? g_whi : g_xhi;
    unsigned* lo = which ? g_wlo : g_xlo;
    int stride = gridDim.x * blockDim.x;
    for (int i = blockIdx.x * blockDim.x + threadIdx.x; i < n4; i += stride) {
        float4 v = ((const float4*)src)[i];
        uint32_t h0 = pack_bf16(v.x, v.y);
        uint32_t h1 = pack_bf16(v.z, v.w);
        float l0 = v.x - __uint_as_float(h0 << 16);
        float l1 = v.y - __uint_as_float(h0 & 0xFFFF0000u);
        float l2 = v.z - __uint_as_float(h1 << 16);
        float l3 = v.w - __uint_as_float(h1 & 0xFFFF0000u);
        hi[2 * i]     = h0;
        hi[2 * i + 1] = h1;
        lo[2 * i]     = pack_bf16(l0, l1);
        lo[2 * i + 1] = pack_bf16(l2, l3);
    }
}

// ============================================================================
// wx_mma: y[m,n] = sum_k x[m,k]*Wih[n,k] + bias[n], split-bf16 HMMA.
// CTA tile 128m x 128n, BK=32, 512 threads (16 warps: wm 0..3, wn 0..3,
// warp tile 32x32 — per-warp structure identical to the proven 256-thr
// version; x/W smem traffic per MMA halves).
// Stage: Ahi/Alo 128x32 bf16 (80B rows), Bhi/Blo 128x32. 40960 B, x2 buf.
// ============================================================================
#define STG_BYTES 40960
#define A_LO_OFF  10240
#define B_OFF     20480
#define B_LO_OFF  30720

__global__ __launch_bounds__(512, 1)
void wx_mma(const float* __restrict__ bias, float* __restrict__ y)
{
    extern __shared__ __align__(16) char smem[];
    const uint32_t sbase = smem_u32(smem);

    const int tid  = threadIdx.x;
    const int wid  = tid >> 5;
    const int lane = tid & 31;
    const int g    = lane >> 2;
    const int t    = lane & 3;
    const int wm   = wid & 3;
    const int wn   = wid >> 2;          // 0..3
    const int m0   = blockIdx.y * 128;
    const int n0   = blockIdx.x * 128;

    float acc[2][4][4];
#pragma unroll
    for (int mf = 0; mf < 2; mf++)
#pragma unroll
        for (int nf = 0; nf < 4; nf++)
#pragma unroll
            for (int c = 0; c < 4; c++) acc[mf][nf][c] = 0.0f;

    auto issue = [&](int st) {
        const uint32_t d = sbase + (st & 1) * STG_BYTES;
        const int k0 = st * 32;
        // A: 1024 x 16B tasks (hi then lo), 512 threads x 2
#pragma unroll
        for (int r = 0; r < 2; r++) {
            int id   = tid + 512 * r;
            int part = id >> 9;
            int rem  = id & 511;
            int row  = rem >> 2;
            int seg  = rem & 3;
            const unsigned* srcb = part ? g_xlo : g_xhi;
            const char* src = (const char*)(srcb +
                ((size_t)(m0 + row) * 1024 + k0) / 2) + seg * 16;
            cp_async16(d + part * A_LO_OFF + row * 80 + seg * 16, src);
        }
        // B: 1024 x 16B tasks (128 rows, hi then lo)
#pragma unroll
        for (int r = 0; r < 2; r++) {
            int id   = tid + 512 * r;
            int part = id >> 9;
            int rem  = id & 511;
            int row  = rem >> 2;
            int seg  = rem & 3;
            const unsigned* srcb = part ? g_wlo : g_whi;
            const char* src = (const char*)(srcb +
                ((size_t)(n0 + row) * 1024 + k0) / 2) + seg * 16;
            cp_async16(d + B_OFF + part * 10240 + row * 80 + seg * 16, src);
        }
        asm volatile("cp.async.commit_group;" ::: "memory");
    };

    issue(0);
    for (int i = 0; i < 32; i++) {
        if (i + 1 < 32) {
            issue(i + 1);
            asm volatile("cp.async.wait_group 1;" ::: "memory");
        } else {
            asm volatile("cp.async.wait_group 0;" ::: "memory");
        }
        __syncthreads();

        const char* sm  = smem + (i & 1) * STG_BYTES;
        const char* Ahi = sm;
        const char* Alo = sm + A_LO_OFF;
        const char* Bhi = sm + B_OFF;
        const char* Blo = sm + B_LO_OFF;

#pragma unroll
        for (int ks = 0; ks < 32; ks += 16) {
            const int colb = (ks + t * 2) * 2;
            uint32_t ah[2][4], al[2][4];
#pragma unroll
            for (int mf = 0; mf < 2; mf++) {
                int r0 = (wm * 32 + mf * 16 + g) * 80;
                int r1 = r0 + 8 * 80;
                ah[mf][0] = *(const uint32_t*)(Ahi + r0 + colb);
                ah[mf][1] = *(const uint32_t*)(Ahi + r1 + colb);
                ah[mf][2] = *(const uint32_t*)(Ahi + r0 + colb + 16);
                ah[mf][3] = *(const uint32_t*)(Ahi + r1 + colb + 16);
                al[mf][0] = *(const uint32_t*)(Alo + r0 + colb);
                al[mf][1] = *(const uint32_t*)(Alo + r1 + colb);
                al[mf][2] = *(const uint32_t*)(Alo + r0 + colb + 16);
                al[mf][3] = *(const uint32_t*)(Alo + r1 + colb + 16);
            }
            uint32_t bh[4][2], bl[4][2];
#pragma unroll
            for (int nf = 0; nf < 4; nf++) {
                int nr = (wn * 32 + nf * 8 + g) * 80;
                bh[nf][0] = *(const uint32_t*)(Bhi + nr + colb);
                bh[nf][1] = *(const uint32_t*)(Bhi + nr + colb + 16);
                bl[nf][0] = *(const uint32_t*)(Blo + nr + colb);
                bl[nf][1] = *(const uint32_t*)(Blo + nr + colb + 16);
            }
#pragma unroll
            for (int mf = 0; mf < 2; mf++)
#pragma unroll
                for (int nf = 0; nf < 4; nf++) {
                    float* c = acc[mf][nf];
                    mma_bf16(c[0], c[1], c[2], c[3],
                             ah[mf][0], ah[mf][1], ah[mf][2], ah[mf][3],
                             bh[nf][0], bh[nf][1]);
                    mma_bf16(c[0], c[1], c[2], c[3],
                             al[mf][0], al[mf][1], al[mf][2], al[mf][3],
                             bh[nf][0], bh[nf][1]);
                    mma_bf16(c[0], c[1], c[2], c[3],
                             ah[mf][0], ah[mf][1], ah[mf][2], ah[mf][3],
                             bl[nf][0], bl[nf][1]);
                }
        }
        __syncthreads();
    }

#pragma unroll
    for (int mf = 0; mf < 2; mf++) {
        int m = m0 + wm * 32 + mf * 16 + g;
#pragma unroll
        for (int nf = 0; nf < 4; nf++) {
            int n = n0 + wn * 32 + nf * 8 + t * 2;
            float2 bv = *(const float2*)(bias + n);
            float* c = acc[mf][nf];
            *(float2*)(y + (size_t)m * H_ + n) =
                make_float2(c[0] + bv.x, c[1] + bv.y);
            *(float2*)(y + (size_t)(m + 8) * H_ + n) =
                make_float2(c[2] + bv.x, c[3] + bv.y);
        }
    }
}

// ============================================================================
// Sync: one-time entry rendezvous (R8 barrier) + per-step monotonic counter.
// Arrive = red.global.release.add (fire-and-forget); wait = poll counter
// >= base + 32*s. base read BEFORE the rendezvous arrive, so no step-0
// arrival (which requires full rendezvous) can precede it. Wrap-safe.
// ============================================================================
__device__ unsigned g_cnt[4 * 32];     // rendezvous counters
__device__ unsigned g_gen[4 * 32];
__device__ unsigned g_step[4 * 32];    // monotonic per-bg step counters

__device__ __forceinline__ void rendezvous(int bg, unsigned nb) {
    __syncthreads();
    if (threadIdx.x == 0) {
        unsigned* cnt = &g_cnt[bg * 32];
        unsigned* gen = &g_gen[bg * 32];
        unsigned g;
        asm volatile("ld.global.acquire.gpu.u32 %0, [%1];" : "=r"(g) : "l"(gen));
        unsigned prev;
        asm volatile("atom.global.acq_rel.gpu.add.u32 %0, [%1], %2;"
                     : "=r"(prev) : "l"(cnt), "r"(1u));
        if (prev == nb - 1) {
            asm volatile("st.global.relaxed.gpu.u32 [%0], %1;" :: "l"(cnt), "r"(0u));
            asm volatile("st.global.release.gpu.u32 [%0], %1;" :: "l"(gen), "r"(g + 1u));
        } else {
            unsigned cur;
            do {
                asm volatile("ld.global.acquire.gpu.u32 %0, [%1];" : "=r"(cur) : "l"(gen));
            } while (cur == g);
        }
    }
    __syncthreads();
}

__device__ __forceinline__ void poll_ge(const unsigned* p, unsigned tgt) {
    unsigned v;
    do {
        asm volatile("ld.global.acquire.gpu.u32 %0, [%1];" : "=r"(v) : "l"(p));
    } while ((int)(v - tgt) < 0);
}

// ============================================================================
// Persistent recurrence via split-bf16 HMMA (R12 compute, new sync).
// ============================================================================
#define WHI_OFF 0
#define WLO_OFF 66048
#define HHI_OFF 132096
#define HLO_OFF 165120
#define RED_OFF 198144
#define RNN_SMEM 200192

__global__ __launch_bounds__(256, 1)
void rnn_persistent(const float* __restrict__ h0,
                    const float* __restrict__ Whh,
                    const float* __restrict__ bias,
                    float* __restrict__ y,
                    float* __restrict__ hlast)
{
    extern __shared__ __align__(16) char smem[];
    const uint32_t sb = smem_u32(smem);
    __shared__ unsigned sh_base;

    const int tid  = threadIdx.x;
    const int w    = tid >> 5;
    const int lane = tid & 31;
    const int nf   = w & 3;
    const int kw   = w >> 2;
    const int ft_id = blockIdx.x;
    const int bg_id = blockIdx.y;
    const int ftile = ft_id * 32;
    const int bg    = bg_id * 16;

    unsigned* step_cnt = &g_step[bg_id * 32];
    if (tid == 0) {
        unsigned b0;
        asm volatile("ld.global.relaxed.gpu.u32 %0, [%1];" : "=r"(b0) : "l"(step_cnt));
        sh_base = b0;
    }

    // ---- one-time: Whh slice -> smem split bf16, 2064B padded rows ----
    {
        const int r = tid >> 3;
        const int part = tid & 7;
        const float* src = Whh + (size_t)(ftile + r) * H_ + part * 128;
        char* dhi = smem + WHI_OFF + r * 2064 + part * 256;
        char* dlo = smem + WLO_OFF + r * 2064 + part * 256;
#pragma unroll
        for (int u = 0; u < 32; u++) {
            float4 v = *(const float4*)(src + u * 4);
            uint32_t h0p = pack_bf16(v.x, v.y);
            uint32_t h1p = pack_bf16(v.z, v.w);
            float l0 = v.x - __uint_as_float(h0p << 16);
            float l1 = v.y - __uint_as_float(h0p & 0xFFFF0000u);
            float l2 = v.z - __uint_as_float(h1p << 16);
            float l3 = v.w - __uint_as_float(h1p & 0xFFFF0000u);
            *(uint2*)(dhi + u * 8) = make_uint2(h0p, h1p);
            *(uint2*)(dlo + u * 8) = make_uint2(pack_bf16(l0, l1), pack_bf16(l2, l3));
        }
    }

    // ---- one-time: ft0 CTA converts h0 (its bg's 16 rows) into g_hb[0] ----
    if (ft_id == 0) {
        const int r = tid >> 4;
        const int part = tid & 15;
        const float* src = h0 + (size_t)(bg + r) * H_ + part * 64;
        unsigned* dhi = &g_hb[0][0][(bg + r) * 512 + part * 32];
        unsigned* dlo = &g_hb[0][1][(bg + r) * 512 + part * 32];
#pragma unroll
        for (int u = 0; u < 16; u++) {
            float4 v = *(const float4*)(src + u * 4);
            uint32_t h0p = pack_bf16(v.x, v.y);
            uint32_t h1p = pack_bf16(v.z, v.w);
            float l0 = v.x - __uint_as_float(h0p << 16);
            float l1 = v.y - __uint_as_float(h0p & 0xFFFF0000u);
            float l2 = v.z - __uint_as_float(h1p << 16);
            float l3 = v.w - __uint_as_float(h1p & 0xFFFF0000u);
            *(uint2*)(dhi + u * 2) = make_uint2(h0p, h1p);
            *(uint2*)(dlo + u * 2) = make_uint2(pack_bf16(l0, l1), pack_bf16(l2, l3));
        }
    }

    // ---- output mapping (kw==0 warps do writeback) ----
    const int mq = lane >> 2;
    const int q  = lane & 3;
    const int fgn  = ftile + nf * 8 + q * 2;
    const int rowA = bg + mq;
    const int rowB = bg + mq + 8;
    float2 bias2 = *(const float2*)(bias + fgn);
    float* yA = y + (size_t)rowA * SH_ + fgn;
    float* yB = y + (size_t)rowB * SH_ + fgn;
    float2 wxA = *(float2*)yA;
    float2 wxB = *(float2*)yB;

    // ---- ldmatrix base addresses ----
    const uint32_t aHiB = sb + HHI_OFF + (uint32_t)(lane & 15) * 2064 +
                          (uint32_t)((lane >> 4) << 4);
    const uint32_t aLoB = aHiB + (HLO_OFF - HHI_OFF);
    const int bl = lane & 15;
    const uint32_t bHiB = sb + WHI_OFF +
                          (uint32_t)(nf * 8 + (bl & 7)) * 2064 +
                          (uint32_t)(((bl >> 3) & 1) << 4);
    const uint32_t bLoB = bHiB + (WLO_OFF - WHI_OFF);

    rendezvous(bg_id, 32);   // anchors base; h0 conversion + wsm visible
    const unsigned base = sh_base;

    for (int s = 0; s < S_; s++) {
        const int p = s & 1;

        // ---- wait for all producers of h[s] ----
        if (s > 0) {
            if (tid == 0) poll_ge(step_cnt, base + 32u * (unsigned)s);
            __syncthreads();
        }

        // ---- stage h (hi+lo bf16) in 4 commit groups of 256 K ----
#pragma unroll
        for (int c = 0; c < 4; c++) {
#pragma unroll
            for (int r = 0; r < 4; r++) {
                int id    = tid + 256 * r;
                int split = id >> 9;
                int rem   = id & 511;
                int row   = rem >> 5;
                int seg   = rem & 31;
                const char* src = (const char*)g_hb[p][split] +
                                  (size_t)(bg + row) * 2048 + c * 512 + seg * 16;
                cp_async16(sb + (split ? HLO_OFF : HHI_OFF) +
                           (uint32_t)(row * 2064 + c * 512 + seg * 16), src);
            }
            asm volatile("cp.async.commit_group;" ::: "memory");
        }

        float c0 = 0.f, c1 = 0.f, c2 = 0.f, c3 = 0.f;

#pragma unroll
        for (int c = 0; c < 4; c++) {
            if      (c == 0) asm volatile("cp.async.wait_group 3;" ::: "memory");
            else if (c == 1) asm volatile("cp.async.wait_group 2;" ::: "memory");
            else if (c == 2) asm volatile("cp.async.wait_group 1;" ::: "memory");
            else             asm volatile("cp.async.wait_group 0;" ::: "memory");
            __syncthreads();

            if ((c >> 1) == kw) {
                const int kc = c * 256;
#pragma unroll 4
                for (int i = 0; i < 16; i++) {
                    const uint32_t kb = (uint32_t)(kc + i * 16) * 2;
                    uint32_t ah0, ah1, ah2, ah3, al0, al1, al2, al3;
                    uint32_t bh0, bh1, blo0, blo1;
                    ldsm_x4(ah0, ah1, ah2, ah3, aHiB + kb);
                    ldsm_x4(al0, al1, al2, al3, aLoB + kb);
                    ldsm_x2(bh0, bh1, bHiB + kb);
                    ldsm_x2(blo0, blo1, bLoB + kb);
                    mma_bf16(c0, c1, c2, c3, ah0, ah1, ah2, ah3, bh0, bh1);
                    mma_bf16(c0, c1, c2, c3, al0, al1, al2, al3, bh0, bh1);
                    mma_bf16(c0, c1, c2, c3, ah0, ah1, ah2, ah3, blo0, blo1);
                }
            }
        }

        // ---- cross-K reduce (2 partials) + writeback ----
        float2* rp = (float2*)(smem + RED_OFF);
        if (kw == 1) {
            rp[(nf * 16 + mq) * 4 + q]     = make_float2(c0, c1);
            rp[(nf * 16 + mq + 8) * 4 + q] = make_float2(c2, c3);
        }
        __syncthreads();
        if (kw == 0) {
            float2 o0 = rp[(nf * 16 + mq) * 4 + q];
            float2 o1 = rp[(nf * 16 + mq + 8) * 4 + q];
            float v00 = tanhf(wxA.x + c0 + o0.x + bias2.x);
            float v01 = tanhf(wxA.y + c1 + o0.y + bias2.y);
            float v10 = tanhf(wxB.x + c2 + o1.x + bias2.x);
            float v11 = tanhf(wxB.y + c3 + o1.y + bias2.y);

            float* ysA = yA + (size_t)s * H_;
            float* ysB = yB + (size_t)s * H_;
            *(float2*)ysA = make_float2(v00, v01);
            *(float2*)ysB = make_float2(v10, v11);

            const int p1 = (s + 1) & 1;
            uint32_t hpA = pack_bf16(v00, v01);
            float lA0 = v00 - __uint_as_float(hpA << 16);
            float lA1 = v01 - __uint_as_float(hpA & 0xFFFF0000u);
            uint32_t hpB = pack_bf16(v10, v11);
            float lB0 = v10 - __uint_as_float(hpB << 16);
            float lB1 = v11 - __uint_as_float(hpB & 0xFFFF0000u);
            g_hb[p1][0][rowA * 512 + (fgn >> 1)] = hpA;
            g_hb[p1][1][rowA * 512 + (fgn >> 1)] = pack_bf16(lA0, lA1);
            g_hb[p1][0][rowB * 512 + (fgn >> 1)] = hpB;
            g_hb[p1][1][rowB * 512 + (fgn >> 1)] = pack_bf16(lB0, lB1);

            if (s == S_ - 1) {
                *(float2*)(hlast + (size_t)rowA * H_ + fgn) = make_float2(v00, v01);
                *(float2*)(hlast + (size_t)rowB * H_ + fgn) = make_float2(v10, v11);
            } else {
                wxA = *(float2*)(ysA + H_);
                wxB = *(float2*)(ysB + H_);
            }
        }

        // ---- publish: fire-and-forget arrive ----
        __syncthreads();   // all h/y stores of this CTA done
        if (tid == 0 && s < S_ - 1) {
            asm volatile("red.global.release.gpu.add.u32 [%0], %1;"
                         :: "l"(step_cnt), "r"(1u) : "memory");
        }
    }
}

// ============================================================================
// Launch: 4 graph nodes. Inputs: x, h, Wih_w, Wih_b, Whh_w, Whh_b.
// Output: y [B,S,H] followed by h_last [B,H].
// ============================================================================
extern "C" void kernel_launch(void* const* d_in, const int* in_sizes, int n_in,
                              void* d_out, int out_size)
{
    const float* x     = (const float*)d_in[0];
    const float* h0    = (const float*)d_in[1];
    const float* Wih_w = (const float*)d_in[2];
    const float* Wih_b = (const float*)d_in[3];
    const float* Whh_w = (const float*)d_in[4];
    const float* Whh_b = (const float*)d_in[5];

    float* y     = (float*)d_out;
    float* hlast = y + (size_t)B_ * S_ * H_;

    const int mma_smem = 2 * STG_BYTES;   // 81920
    cudaFuncSetAttribute(wx_mma, cudaFuncAttributeMaxDynamicSharedMemorySize,
                         mma_smem);
    cudaFuncSetAttribute(rnn_persistent,
                         cudaFuncAttributeMaxDynamicSharedMemorySize, RNN_SMEM);

    cvt_split<<<8192, 256>>>(x, 0, 16777216);      // x: 16M float4
    cvt_split<<<1024, 256>>>(Wih_w, 1, 262144);    // W: 256K float4
    wx_mma<<<dim3(8, 512), 512, mma_smem>>>(Wih_b, y);
    rnn_persistent<<<dim3(32, 4), 256, RNN_SMEM>>>(h0, Whh_w, Whh_b, y, hlast);
}

// round 14
// speedup vs baseline: 1.9493x; 1.1644x over previous
#include <cuda_runtime.h>
#include <cstdint>

typedef unsigned long long ULL;

#define B_   64
#define S_   1024
#define I_   1024
#define H_   1024
#define SH_  (S_ * H_)   // 1048576

// ---- helpers ----
__device__ __forceinline__ void cp_async16(uint32_t smem_addr, const void* gptr) {
    asm volatile("cp.async.cg.shared.global [%0], [%1], 16;"
                 :: "r"(smem_addr), "l"(gptr));
}
__device__ __forceinline__ uint32_t smem_u32(const void* p) {
    return (uint32_t)__cvta_generic_to_shared(p);
}
// pack: low half = bf16(v0), high half = bf16(v1)
__device__ __forceinline__ uint32_t pack_bf16(float v0, float v1) {
    uint32_t r;
    asm("cvt.rn.bf16x2.f32 %0, %1, %2;" : "=r"(r) : "f"(v1), "f"(v0));
    return r;
}
__device__ __forceinline__ void ldsm_x4(uint32_t& r0, uint32_t& r1,
                                        uint32_t& r2, uint32_t& r3, uint32_t a) {
    asm volatile("ldmatrix.sync.aligned.m8n8.x4.shared.b16 {%0,%1,%2,%3}, [%4];"
                 : "=r"(r0), "=r"(r1), "=r"(r2), "=r"(r3) : "r"(a));
}
__device__ __forceinline__ void ldsm_x2(uint32_t& r0, uint32_t& r1, uint32_t a) {
    asm volatile("ldmatrix.sync.aligned.m8n8.x2.shared.b16 {%0,%1}, [%2];"
                 : "=r"(r0), "=r"(r1) : "r"(a));
}
__device__ __forceinline__ void mma_bf16(float& c0, float& c1, float& c2, float& c3,
                                         uint32_t a0, uint32_t a1, uint32_t a2, uint32_t a3,
                                         uint32_t b0, uint32_t b1) {
    asm volatile("mma.sync.aligned.m16n8k16.row.col.f32.bf16.bf16.f32 "
                 "{%0,%1,%2,%3}, {%4,%5,%6,%7}, {%8,%9}, {%0,%1,%2,%3};"
                 : "+f"(c0), "+f"(c1), "+f"(c2), "+f"(c3)
                 : "r"(a0), "r"(a1), "r"(a2), "r"(a3), "r"(b0), "r"(b1));
}
#define HALF_BAR(id) asm volatile("bar.sync %0, 128;" :: "r"(id) : "memory")

// ============================================================================
// Static scratch.
// ============================================================================
__device__ unsigned g_xhi[33554432];   // x split-bf16 (wx path)
__device__ unsigned g_xlo[33554432];
__device__ unsigned g_whi[524288];     // Wih split-bf16
__device__ unsigned g_wlo[524288];
__device__ unsigned g_hb[2][2][32768]; // h state, [parity][hi/lo][64 rows x 512 u32]

// ============================================================================
// Convert fp32 -> (hi, lo) bf16 pairs. which: 0 = x, 1 = W. (wx path)
// ============================================================================
__global__ void cvt_split(const float* __restrict__ src, int which, int n4)
{
    unsigned* hi = which ? g_whi : g_xhi;
    unsigned* lo = which ? g_wlo : g_xlo;
    int stride = gridDim.x * blockDim.x;
    for (int i = blockIdx.x * blockDim.x + threadIdx.x; i < n4; i += stride) {
        float4 v = ((const float4*)src)[i];
        uint32_t h0 = pack_bf16(v.x, v.y);
        uint32_t h1 = pack_bf16(v.z, v.w);
        float l0 = v.x - __uint_as_float(h0 << 16);
        float l1 = v.y - __uint_as_float(h0 & 0xFFFF0000u);
        float l2 = v.z - __uint_as_float(h1 << 16);
        float l3 = v.w - __uint_as_float(h1 & 0xFFFF0000u);
        hi[2 * i]     = h0;
        hi[2 * i + 1] = h1;
        lo[2 * i]     = pack_bf16(l0, l1);
        lo[2 * i + 1] = pack_bf16(l2, l3);
    }
}

// ============================================================================
// wx_mma (unchanged from R13).
// ============================================================================
#define STG_BYTES 40960
#define A_LO_OFF  10240
#define B_OFF     20480
#define B_LO_OFF  30720

__global__ __launch_bounds__(512, 1)
void wx_mma(const float* __restrict__ bias, float* __restrict__ y)
{
    extern __shared__ __align__(16) char smem[];
    const uint32_t sbase = smem_u32(smem);

    const int tid  = threadIdx.x;
    const int wid  = tid >> 5;
    const int lane = tid & 31;
    const int g    = lane >> 2;
    const int t    = lane & 3;
    const int wm   = wid & 3;
    const int wn   = wid >> 2;
    const int m0   = blockIdx.y * 128;
    const int n0   = blockIdx.x * 128;

    float acc[2][4][4];
#pragma unroll
    for (int mf = 0; mf < 2; mf++)
#pragma unroll
        for (int nf = 0; nf < 4; nf++)
#pragma unroll
            for (int c = 0; c < 4; c++) acc[mf][nf][c] = 0.0f;

    auto issue = [&](int st) {
        const uint32_t d = sbase + (st & 1) * STG_BYTES;
        const int k0 = st * 32;
#pragma unroll
        for (int r = 0; r < 2; r++) {
            int id   = tid + 512 * r;
            int part = id >> 9;
            int rem  = id & 511;
            int row  = rem >> 2;
            int seg  = rem & 3;
            const unsigned* srcb = part ? g_xlo : g_xhi;
            const char* src = (const char*)(srcb +
                ((size_t)(m0 + row) * 1024 + k0) / 2) + seg * 16;
            cp_async16(d + part * A_LO_OFF + row * 80 + seg * 16, src);
        }
#pragma unroll
        for (int r = 0; r < 2; r++) {
            int id   = tid + 512 * r;
            int part = id >> 9;
            int rem  = id & 511;
            int row  = rem >> 2;
            int seg  = rem & 3;
            const unsigned* srcb = part ? g_wlo : g_whi;
            const char* src = (const char*)(srcb +
                ((size_t)(n0 + row) * 1024 + k0) / 2) + seg * 16;
            cp_async16(d + B_OFF + part * 10240 + row * 80 + seg * 16, src);
        }
        asm volatile("cp.async.commit_group;" ::: "memory");
    };

    issue(0);
    for (int i = 0; i < 32; i++) {
        if (i + 1 < 32) {
            issue(i + 1);
            asm volatile("cp.async.wait_group 1;" ::: "memory");
        } else {
            asm volatile("cp.async.wait_group 0;" ::: "memory");
        }
        __syncthreads();

        const char* sm  = smem + (i & 1) * STG_BYTES;
        const char* Ahi = sm;
        const char* Alo = sm + A_LO_OFF;
        const char* Bhi = sm + B_OFF;
        const char* Blo = sm + B_LO_OFF;

#pragma unroll
        for (int ks = 0; ks < 32; ks += 16) {
            const int colb = (ks + t * 2) * 2;
            uint32_t ah[2][4], al[2][4];
#pragma unroll
            for (int mf = 0; mf < 2; mf++) {
                int r0 = (wm * 32 + mf * 16 + g) * 80;
                int r1 = r0 + 8 * 80;
                ah[mf][0] = *(const uint32_t*)(Ahi + r0 + colb);
                ah[mf][1] = *(const uint32_t*)(Ahi + r1 + colb);
                ah[mf][2] = *(const uint32_t*)(Ahi + r0 + colb + 16);
                ah[mf][3] = *(const uint32_t*)(Ahi + r1 + colb + 16);
                al[mf][0] = *(const uint32_t*)(Alo + r0 + colb);
                al[mf][1] = *(const uint32_t*)(Alo + r1 + colb);
                al[mf][2] = *(const uint32_t*)(Alo + r0 + colb + 16);
                al[mf][3] = *(const uint32_t*)(Alo + r1 + colb + 16);
            }
            uint32_t bh[4][2], bl[4][2];
#pragma unroll
            for (int nf = 0; nf < 4; nf++) {
                int nr = (wn * 32 + nf * 8 + g) * 80;
                bh[nf][0] = *(const uint32_t*)(Bhi + nr + colb);
                bh[nf][1] = *(const uint32_t*)(Bhi + nr + colb + 16);
                bl[nf][0] = *(const uint32_t*)(Blo + nr + colb);
                bl[nf][1] = *(const uint32_t*)(Blo + nr + colb + 16);
            }
#pragma unroll
            for (int mf = 0; mf < 2; mf++)
#pragma unroll
                for (int nf = 0; nf < 4; nf++) {
                    float* c = acc[mf][nf];
                    mma_bf16(c[0], c[1], c[2], c[3],
                             ah[mf][0], ah[mf][1], ah[mf][2], ah[mf][3],
                             bh[nf][0], bh[nf][1]);
                    mma_bf16(c[0], c[1], c[2], c[3],
                             al[mf][0], al[mf][1], al[mf][2], al[mf][3],
                             bh[nf][0], bh[nf][1]);
                    mma_bf16(c[0], c[1], c[2], c[3],
                             ah[mf][0], ah[mf][1], ah[mf][2], ah[mf][3],
                             bl[nf][0], bl[nf][1]);
                }
        }
        __syncthreads();
    }

#pragma unroll
    for (int mf = 0; mf < 2; mf++) {
        int m = m0 + wm * 32 + mf * 16 + g;
#pragma unroll
        for (int nf = 0; nf < 4; nf++) {
            int n = n0 + wn * 32 + nf * 8 + t * 2;
            float2 bv = *(const float2*)(bias + n);
            float* c = acc[mf][nf];
            *(float2*)(y + (size_t)m * H_ + n) =
                make_float2(c[0] + bv.x, c[1] + bv.y);
            *(float2*)(y + (size_t)(m + 8) * H_ + n) =
                make_float2(c[2] + bv.x, c[3] + bv.y);
        }
    }
}

// ============================================================================
// Sync: entry rendezvous + monotonic per-bg step counter (R13, known good).
// ============================================================================
__device__ unsigned g_cnt[4 * 32];
__device__ unsigned g_gen[4 * 32];
__device__ unsigned g_step[4 * 32];

__device__ __forceinline__ void rendezvous(int bg, unsigned nb) {
    __syncthreads();
    if (threadIdx.x == 0) {
        unsigned* cnt = &g_cnt[bg * 32];
        unsigned* gen = &g_gen[bg * 32];
        unsigned g;
        asm volatile("ld.global.acquire.gpu.u32 %0, [%1];" : "=r"(g) : "l"(gen));
        unsigned prev;
        asm volatile("atom.global.acq_rel.gpu.add.u32 %0, [%1], %2;"
                     : "=r"(prev) : "l"(cnt), "r"(1u));
        if (prev == nb - 1) {
            asm volatile("st.global.relaxed.gpu.u32 [%0], %1;" :: "l"(cnt), "r"(0u));
            asm volatile("st.global.release.gpu.u32 [%0], %1;" :: "l"(gen), "r"(g + 1u));
        } else {
            unsigned cur;
            do {
                asm volatile("ld.global.acquire.gpu.u32 %0, [%1];" : "=r"(cur) : "l"(gen));
            } while (cur == g);
        }
    }
    __syncthreads();
}

__device__ __forceinline__ void poll_ge(const unsigned* p, unsigned tgt) {
    unsigned v;
    do {
        asm volatile("ld.global.acquire.gpu.u32 %0, [%1];" : "=r"(v) : "l"(p));
    } while ((int)(v - tgt) < 0);
}

// ============================================================================
// Persistent recurrence, split-bf16 HMMA, TWO INDEPENDENT HALF-PIPELINES.
// kw0 = warps 0..3 (tid<128): K[0,512); kw1 = warps 4..7: K[512,1024).
// Each half polls, stages its own K-range, and computes concurrently
// (named barriers); only the partial exchange + arrive are block-wide.
// Writeback split: kw0 produces rowA (batches mq), kw1 rowB (mq+8).
// ============================================================================
#define WHI_OFF 0
#define WLO_OFF 66048
#define HHI_OFF 132096
#define HLO_OFF 165120
#define RED_OFF 198144
#define RNN_SMEM 200192

__global__ __launch_bounds__(256, 1)
void rnn_persistent(const float* __restrict__ h0,
                    const float* __restrict__ Whh,
                    const float* __restrict__ bias,
                    float* __restrict__ y,
                    float* __restrict__ hlast)
{
    extern __shared__ __align__(16) char smem[];
    const uint32_t sb = smem_u32(smem);
    __shared__ unsigned sh_base;

    const int tid  = threadIdx.x;
    const int w    = tid >> 5;
    const int lane = tid & 31;
    const int nf   = w & 3;
    const int kw   = w >> 2;
    const int htid = tid & 127;            // id within half
    const int ft_id = blockIdx.x;
    const int bg_id = blockIdx.y;
    const int ftile = ft_id * 32;
    const int bg    = bg_id * 16;

    unsigned* step_cnt = &g_step[bg_id * 32];
    if (tid == 0) {
        unsigned b0;
        asm volatile("ld.global.relaxed.gpu.u32 %0, [%1];" : "=r"(b0) : "l"(step_cnt));
        sh_base = b0;
    }

    // ---- one-time: Whh slice -> smem split bf16, 2064B padded rows ----
    {
        const int r = tid >> 3;
        const int part = tid & 7;
        const float* src = Whh + (size_t)(ftile + r) * H_ + part * 128;
        char* dhi = smem + WHI_OFF + r * 2064 + part * 256;
        char* dlo = smem + WLO_OFF + r * 2064 + part * 256;
#pragma unroll
        for (int u = 0; u < 32; u++) {
            float4 v = *(const float4*)(src + u * 4);
            uint32_t h0p = pack_bf16(v.x, v.y);
            uint32_t h1p = pack_bf16(v.z, v.w);
            float l0 = v.x - __uint_as_float(h0p << 16);
            float l1 = v.y - __uint_as_float(h0p & 0xFFFF0000u);
            float l2 = v.z - __uint_as_float(h1p << 16);
            float l3 = v.w - __uint_as_float(h1p & 0xFFFF0000u);
            *(uint2*)(dhi + u * 8) = make_uint2(h0p, h1p);
            *(uint2*)(dlo + u * 8) = make_uint2(pack_bf16(l0, l1), pack_bf16(l2, l3));
        }
    }

    // ---- one-time: ft0 CTA converts h0 (its bg's 16 rows) into g_hb[0] ----
    if (ft_id == 0) {
        const int r = tid >> 4;
        const int part = tid & 15;
        const float* src = h0 + (size_t)(bg + r) * H_ + part * 64;
        unsigned* dhi = &g_hb[0][0][(bg + r) * 512 + part * 32];
        unsigned* dlo = &g_hb[0][1][(bg + r) * 512 + part * 32];
#pragma unroll
        for (int u = 0; u < 16; u++) {
            float4 v = *(const float4*)(src + u * 4);
            uint32_t h0p = pack_bf16(v.x, v.y);
            uint32_t h1p = pack_bf16(v.z, v.w);
            float l0 = v.x - __uint_as_float(h0p << 16);
            float l1 = v.y - __uint_as_float(h0p & 0xFFFF0000u);
            float l2 = v.z - __uint_as_float(h1p << 16);
            float l3 = v.w - __uint_as_float(h1p & 0xFFFF0000u);
            *(uint2*)(dhi + u * 2) = make_uint2(h0p, h1p);
            *(uint2*)(dlo + u * 2) = make_uint2(pack_bf16(l0, l1), pack_bf16(l2, l3));
        }
    }

    // ---- output mapping ----
    const int mq = lane >> 2;
    const int q  = lane & 3;
    const int fgn  = ftile + nf * 8 + q * 2;
    const int rowA = bg + mq;
    const int rowB = bg + mq + 8;
    float2 bias2 = *(const float2*)(bias + fgn);
    float* yA = y + (size_t)rowA * SH_ + fgn;
    float* yB = y + (size_t)rowB * SH_ + fgn;
    // kw0 threads track wxA (rowA); kw1 threads track wxB (rowB)
    float2 wx2 = (kw == 0) ? *(float2*)yA : *(float2*)yB;

    // ---- ldmatrix base addresses ----
    const uint32_t aHiB = sb + HHI_OFF + (uint32_t)(lane & 15) * 2064 +
                          (uint32_t)((lane >> 4) << 4);
    const uint32_t aLoB = aHiB + (HLO_OFF - HHI_OFF);
    const int bl = lane & 15;
    const uint32_t bHiB = sb + WHI_OFF +
                          (uint32_t)(nf * 8 + (bl & 7)) * 2064 +
                          (uint32_t)(((bl >> 3) & 1) << 4);
    const uint32_t bLoB = bHiB + (WLO_OFF - WHI_OFF);

    // exchange buffers: kw0 deposits rowB partials, kw1 deposits rowA partials
    float2* bufA = (float2*)(smem + RED_OFF);        // 128 float2 (kw0 -> kw1)
    float2* bufB = bufA + 128;                       // 128 float2 (kw1 -> kw0)
    const int slot = (nf * 8 + mq) * 4 + q;

    const int kbase = kw * 512;                      // this half's K offset
    const int barid = 1 + kw;

    rendezvous(bg_id, 32);   // anchors base; h0 conversion + W smem visible
    const unsigned base = sh_base;

    for (int s = 0; s < S_; s++) {
        const int p = s & 1;

        // ---- per-half wait for producers of h[s] ----
        if (s > 0) {
            if (htid == 0) poll_ge(step_cnt, base + 32u * (unsigned)s);
            HALF_BAR(barid);
        }

        // ---- stage this half's h K-range: 2 chunks of 256 K (hi+lo) ----
#pragma unroll
        for (int c = 0; c < 2; c++) {
            const int koffB = (kbase + c * 256) * 2;   // byte offset in row
#pragma unroll
            for (int r = 0; r < 8; r++) {
                int t     = r * 128 + htid;            // 0..1023
                int split = t >> 9;
                int rem   = t & 511;
                int row   = rem >> 5;
                int seg   = rem & 31;
                const char* src = (const char*)g_hb[p][split] +
                                  (size_t)(bg + row) * 2048 + koffB + seg * 16;
                cp_async16(sb + (split ? HLO_OFF : HHI_OFF) +
                           (uint32_t)(row * 2064 + koffB + seg * 16), src);
            }
            asm volatile("cp.async.commit_group;" ::: "memory");
        }

        float c0 = 0.f, c1 = 0.f, c2 = 0.f, c3 = 0.f;

#pragma unroll
        for (int c = 0; c < 2; c++) {
            if (c == 0) asm volatile("cp.async.wait_group 1;" ::: "memory");
            else        asm volatile("cp.async.wait_group 0;" ::: "memory");
            HALF_BAR(barid);

            const int kc = kbase + c * 256;
#pragma unroll 4
            for (int i = 0; i < 16; i++) {
                const uint32_t kb = (uint32_t)(kc + i * 16) * 2;
                uint32_t ah0, ah1, ah2, ah3, al0, al1, al2, al3;
                uint32_t bh0, bh1, blo0, blo1;
                ldsm_x4(ah0, ah1, ah2, ah3, aHiB + kb);
                ldsm_x4(al0, al1, al2, al3, aLoB + kb);
                ldsm_x2(bh0, bh1, bHiB + kb);
                ldsm_x2(blo0, blo1, bLoB + kb);
                mma_bf16(c0, c1, c2, c3, ah0, ah1, ah2, ah3, bh0, bh1);
                mma_bf16(c0, c1, c2, c3, al0, al1, al2, al3, bh0, bh1);
                mma_bf16(c0, c1, c2, c3, ah0, ah1, ah2, ah3, blo0, blo1);
            }
        }

        // ---- symmetric partial exchange ----
        if (kw == 0) bufA[slot] = make_float2(c2, c3);   // rowB partial -> kw1
        else         bufB[slot] = make_float2(c0, c1);   // rowA partial -> kw0
        __syncthreads();

        // ---- writeback: kw0 handles rowA, kw1 handles rowB ----
        const int p1 = (s + 1) & 1;
        if (kw == 0) {
            float2 o = bufB[slot];
            float v0 = tanhf(wx2.x + c0 + o.x + bias2.x);
            float v1 = tanhf(wx2.y + c1 + o.y + bias2.y);
            float* ysA = yA + (size_t)s * H_;
            *(float2*)ysA = make_float2(v0, v1);
            uint32_t hp = pack_bf16(v0, v1);
            float l0 = v0 - __uint_as_float(hp << 16);
            float l1 = v1 - __uint_as_float(hp & 0xFFFF0000u);
            g_hb[p1][0][rowA * 512 + (fgn >> 1)] = hp;
            g_hb[p1][1][rowA * 512 + (fgn >> 1)] = pack_bf16(l0, l1);
            if (s == S_ - 1)
                *(float2*)(hlast + (size_t)rowA * H_ + fgn) = make_float2(v0, v1);
            else
                wx2 = *(float2*)(ysA + H_);
        } else {
            float2 o = bufA[slot];
            float v0 = tanhf(wx2.x + c2 + o.x + bias2.x);
            float v1 = tanhf(wx2.y + c3 + o.y + bias2.y);
            float* ysB = yB + (size_t)s * H_;
            *(float2*)ysB = make_float2(v0, v1);
            uint32_t hp = pack_bf16(v0, v1);
            float l0 = v0 - __uint_as_float(hp << 16);
            float l1 = v1 - __uint_as_float(hp & 0xFFFF0000u);
            g_hb[p1][0][rowB * 512 + (fgn >> 1)] = hp;
            g_hb[p1][1][rowB * 512 + (fgn >> 1)] = pack_bf16(l0, l1);
            if (s == S_ - 1)
                *(float2*)(hlast + (size_t)rowB * H_ + fgn) = make_float2(v0, v1);
            else
                wx2 = *(float2*)(ysB + H_);
        }

        // ---- publish: fire-and-forget arrive after all stores visible ----
        __syncthreads();
        if (tid == 0 && s < S_ - 1) {
            asm volatile("red.global.release.gpu.add.u32 [%0], %1;"
                         :: "l"(step_cnt), "r"(1u) : "memory");
        }
    }
}

// ============================================================================
// Launch: 4 graph nodes. Inputs: x, h, Wih_w, Wih_b, Whh_w, Whh_b.
// Output: y [B,S,H] followed by h_last [B,H].
// ============================================================================
extern "C" void kernel_launch(void* const* d_in, const int* in_sizes, int n_in,
                              void* d_out, int out_size)
{
    const float* x     = (const float*)d_in[0];
    const float* h0    = (const float*)d_in[1];
    const float* Wih_w = (const float*)d_in[2];
    const float* Wih_b = (const float*)d_in[3];
    const float* Whh_w = (const float*)d_in[4];
    const float* Whh_b = (const float*)d_in[5];

    float* y     = (float*)d_out;
    float* hlast = y + (size_t)B_ * S_ * H_;

    const int mma_smem = 2 * STG_BYTES;   // 81920
    cudaFuncSetAttribute(wx_mma, cudaFuncAttributeMaxDynamicSharedMemorySize,
                         mma_smem);
    cudaFuncSetAttribute(rnn_persistent,
                         cudaFuncAttributeMaxDynamicSharedMemorySize, RNN_SMEM);

    cvt_split<<<8192, 256>>>(x, 0, 16777216);      // x: 16M float4
    cvt_split<<<1024, 256>>>(Wih_w, 1, 262144);    // W: 256K float4
    wx_mma<<<dim3(8, 512), 512, mma_smem>>>(Wih_b, y);
    rnn_persistent<<<dim3(32, 4), 256, RNN_SMEM>>>(h0, Whh_w, Whh_b, y, hlast);
}